// round 9
// baseline (speedup 1.0000x reference)
#include <cuda_runtime.h>
#include <math.h>

#define D_MODEL   1024
#define N_HEADS   16
#define HEAD_DIM  64
#define D_FF      4096
#define SEQ       2048
#define BATCH     2
#define M_ROWS    (BATCH * SEQ)   // 4096
#define EPS       1e-5f

// ---------------------------------------------------------------------------
// Scratch (device globals -- no allocations allowed)
// ---------------------------------------------------------------------------
__device__ float g_nx [M_ROWS * D_MODEL];   // LN1 out, tf32-rounded, k-permuted
__device__ float g_q  [M_ROWS * D_MODEL];   // [B,H,S,d], tf32-rounded
__device__ float g_k  [M_ROWS * D_MODEL];
__device__ float g_v  [M_ROWS * D_MODEL];
__device__ float g_ctx[M_ROWS * D_MODEL];   // [B,S,D], tf32-rounded, k-permuted
__device__ float g_x2 [M_ROWS * D_MODEL];   // fp32 exact
__device__ float g_nx2[M_ROWS * D_MODEL];   // tf32-rounded, k-permuted
__device__ float g_ffh[M_ROWS * D_FF];      // tf32-rounded, k-permuted
// transposed+rounded+permuted weights: [N][K]
__device__ float g_wqt[D_MODEL * D_MODEL];
__device__ float g_wkt[D_MODEL * D_MODEL];
__device__ float g_wvt[D_MODEL * D_MODEL];
__device__ float g_wot[D_MODEL * D_MODEL];
__device__ float g_w1t[D_FF * D_MODEL];
__device__ float g_w2t[D_MODEL * D_FF];

__device__ __forceinline__ unsigned f2tf32(float x) {
    unsigned y;
    asm("cvt.rna.tf32.f32 %0, %1;" : "=r"(y) : "f"(x));
    return y;
}
__device__ __forceinline__ float roundtf(float x) {
    return __uint_as_float(f2tf32(x));
}
// k-permutation within each 32-wide window: k -> (k%4)*8 + k/4
__device__ __forceinline__ int kperm(int c) {
    int w = c >> 5, i = c & 31;
    return (w << 5) + ((i & 3) << 3) + (i >> 2);
}

__device__ __forceinline__ void mma_tf32(float* c, const unsigned* a, const unsigned* b) {
    asm volatile(
        "mma.sync.aligned.m16n8k8.row.col.f32.tf32.tf32.f32 "
        "{%0,%1,%2,%3}, {%4,%5,%6,%7}, {%8,%9}, {%0,%1,%2,%3};"
        : "+f"(c[0]), "+f"(c[1]), "+f"(c[2]), "+f"(c[3])
        : "r"(a[0]), "r"(a[1]), "r"(a[2]), "r"(a[3]),
          "r"(b[0]), "r"(b[1]));
}

#define CP_ASYNC16(dst, src) \
    asm volatile("cp.async.cg.shared.global [%0], [%1], 16;" :: "r"(dst), "l"(src))

// ---------------------------------------------------------------------------
// Weight prep: Bt[n][perm(k)] = round_tf32(w[k][n]).  32x32 tiles.
// ---------------------------------------------------------------------------
__global__ __launch_bounds__(256) void wprep_kernel(
    const float* __restrict__ w, float* __restrict__ bt, int K, int N)
{
    __shared__ float s[32][33];
    int n0 = blockIdx.x * 32;
    int k0 = blockIdx.y * 32;
    int t  = threadIdx.x;
    {
        int kl = t >> 3, n4 = (t & 7) * 4;
        float4 v = *reinterpret_cast<const float4*>(w + (size_t)(k0 + kl) * N + n0 + n4);
        s[kl][n4 + 0] = v.x; s[kl][n4 + 1] = v.y;
        s[kl][n4 + 2] = v.z; s[kl][n4 + 3] = v.w;
    }
    __syncthreads();
    {
        int nl = t >> 3, j4 = (t & 7) * 4;
        float* dst = bt + (size_t)(n0 + nl) * K + k0;
        #pragma unroll
        for (int b = 0; b < 4; b++) {
            int j = j4 + b;
            dst[((j & 3) << 3) + (j >> 2)] = roundtf(s[j][nl]);
        }
    }
}

// ---------------------------------------------------------------------------
// LayerNorm -> tf32-rounded, k-permuted output (consumed as GEMM A)
// ---------------------------------------------------------------------------
__global__ __launch_bounds__(256) void ln_kernel(
    const float* __restrict__ x, const float* __restrict__ g,
    const float* __restrict__ b, float* __restrict__ out)
{
    int row = blockIdx.x;
    int t   = threadIdx.x;
    const float4* xr = reinterpret_cast<const float4*>(x + (size_t)row * D_MODEL);
    float4 v = xr[t];
    float s  = v.x + v.y + v.z + v.w;
    float ss = v.x * v.x + v.y * v.y + v.z * v.z + v.w * v.w;
    #pragma unroll
    for (int o = 16; o > 0; o >>= 1) {
        s  += __shfl_xor_sync(0xffffffffu, s,  o);
        ss += __shfl_xor_sync(0xffffffffu, ss, o);
    }
    __shared__ float shs[8], shss[8];
    int w = t >> 5;
    if ((t & 31) == 0) { shs[w] = s; shss[w] = ss; }
    __syncthreads();
    float tot = 0.f, tot2 = 0.f;
    #pragma unroll
    for (int i = 0; i < 8; i++) { tot += shs[i]; tot2 += shss[i]; }
    float mu  = tot * (1.0f / D_MODEL);
    float var = tot2 * (1.0f / D_MODEL) - mu * mu;
    float inv = rsqrtf(var + EPS);
    float4 gv = reinterpret_cast<const float4*>(g)[t];
    float4 bv = reinterpret_cast<const float4*>(b)[t];
    float o0 = (v.x - mu) * inv * gv.x + bv.x;
    float o1 = (v.y - mu) * inv * gv.y + bv.y;
    float o2 = (v.z - mu) * inv * gv.z + bv.z;
    float o3 = (v.w - mu) * inv * gv.w + bv.w;
    // permuted scatter: cols 4t..4t+3 -> base + {0,8,16,24}
    float* dst = out + (size_t)row * D_MODEL + ((t >> 3) << 5) + (t & 7);
    dst[0]  = roundtf(o0);
    dst[8]  = roundtf(o1);
    dst[16] = roundtf(o2);
    dst[24] = roundtf(o3);
}

// ---------------------------------------------------------------------------
// TF32 GEMM: 128x128x32 tile, 8 warps (warp tile 64x32), cp.async double
// buffer. A [M][K] k-permuted rows; Bt [N][K] k-permuted rows. Fragments
// loaded as LDS.128 (8 contiguous floats cover all 4 k8-steps).
// MODE 1: round(bias+acc) head-scatter; 2: round(relu) k-permuted;
// MODE 3: acc+bias+res (fp32, linear).
// ---------------------------------------------------------------------------
#define BM 128
#define BN 128
#define BK 32
#define TS 36   // tile stride; quad-bank = (2*tg + 9*g) % 8 -> conflict-free
#define STAGE (BM * TS)
#define GEMM_SMEM (2 * 2 * STAGE * 4)

template<int MODE>
__global__ __launch_bounds__(256) void mmagemm_kernel(
    const float* __restrict__ A, const float* __restrict__ Bt,
    const float* __restrict__ bias, const float* __restrict__ res,
    float* __restrict__ C, int Ndim, int Kdim)
{
    extern __shared__ float smf[];
    float* As = smf;                 // [2][128][TS]
    float* Bs = smf + 2 * STAGE;     // [2][128][TS]

    int tid  = threadIdx.x;
    int lane = tid & 31;
    int warp = tid >> 5;
    int wm   = warp >> 2;
    int wn   = warp & 3;
    int g    = lane >> 2;
    int tg   = lane & 3;
    int row0 = blockIdx.y * BM;
    int col0 = blockIdx.x * BN;

    float acc[4][4][4] = {};

    auto issue_stage = [&](int kb, int buf) {
        float* Ab = As + buf * STAGE;
        float* Bb = Bs + buf * STAGE;
        #pragma unroll
        for (int p = 0; p < 4; p++) {
            int f = tid + p * 256, r = f >> 3, k4 = (f & 7) * 4;
            unsigned d = (unsigned)__cvta_generic_to_shared(Ab + r * TS + k4);
            CP_ASYNC16(d, A + (size_t)(row0 + r) * Kdim + kb + k4);
        }
        #pragma unroll
        for (int p = 0; p < 4; p++) {
            int f = tid + p * 256, r = f >> 3, k4 = (f & 7) * 4;
            unsigned d = (unsigned)__cvta_generic_to_shared(Bb + r * TS + k4);
            CP_ASYNC16(d, Bt + (size_t)(col0 + r) * Kdim + kb + k4);
        }
        asm volatile("cp.async.commit_group;");
    };

    issue_stage(0, 0);
    int nk = Kdim / BK;
    for (int t = 0; t < nk; t++) {
        int buf = t & 1;
        if (t + 1 < nk) {
            issue_stage((t + 1) * BK, buf ^ 1);
            asm volatile("cp.async.wait_group 1;");
        } else {
            asm volatile("cp.async.wait_group 0;");
        }
        __syncthreads();
        const float* Ab = As + buf * STAGE;
        const float* Bb = Bs + buf * STAGE;
        #pragma unroll
        for (int half = 0; half < 2; half++) {
            uint4 av0[4], av1[4], bv[4];
            #pragma unroll
            for (int mt = 0; mt < 4; mt++) {
                int r = wm * 64 + mt * 16 + g;
                av0[mt] = *reinterpret_cast<const uint4*>(Ab + r * TS + tg * 8 + half * 4);
                av1[mt] = *reinterpret_cast<const uint4*>(Ab + (r + 8) * TS + tg * 8 + half * 4);
            }
            #pragma unroll
            for (int nt = 0; nt < 4; nt++) {
                int n = wn * 32 + nt * 8 + g;
                bv[nt] = *reinterpret_cast<const uint4*>(Bb + n * TS + tg * 8 + half * 4);
            }
            #pragma unroll
            for (int s2 = 0; s2 < 2; s2++) {
                #pragma unroll
                for (int mt = 0; mt < 4; mt++) {
                    unsigned a0[4] = {
                        s2 ? av0[mt].z : av0[mt].x,
                        s2 ? av1[mt].z : av1[mt].x,
                        s2 ? av0[mt].w : av0[mt].y,
                        s2 ? av1[mt].w : av1[mt].y };
                    #pragma unroll
                    for (int nt = 0; nt < 4; nt++) {
                        unsigned b0[2] = {
                            s2 ? bv[nt].z : bv[nt].x,
                            s2 ? bv[nt].w : bv[nt].y };
                        mma_tf32(acc[mt][nt], a0, b0);
                    }
                }
            }
        }
        __syncthreads();
    }

    #pragma unroll
    for (int mt = 0; mt < 4; mt++) {
        int m1 = row0 + wm * 64 + mt * 16 + g;
        int m2 = m1 + 8;
        #pragma unroll
        for (int nt = 0; nt < 4; nt++) {
            int n = col0 + wn * 32 + nt * 8 + 2 * tg;
            float2 bb = *reinterpret_cast<const float2*>(bias + n);
            float2 o1, o2;
            o1.x = acc[mt][nt][0] + bb.x;
            o1.y = acc[mt][nt][1] + bb.y;
            o2.x = acc[mt][nt][2] + bb.x;
            o2.y = acc[mt][nt][3] + bb.y;
            if (MODE == 2) {
                // relu + round + k-permute scatter (feeds FF2 as A)
                int p0 = kperm(n), p1 = kperm(n + 1);
                C[(size_t)m1 * Ndim + p0] = roundtf(fmaxf(o1.x, 0.f));
                C[(size_t)m1 * Ndim + p1] = roundtf(fmaxf(o1.y, 0.f));
                C[(size_t)m2 * Ndim + p0] = roundtf(fmaxf(o2.x, 0.f));
                C[(size_t)m2 * Ndim + p1] = roundtf(fmaxf(o2.y, 0.f));
            } else if (MODE == 3) {
                float2 r1 = *reinterpret_cast<const float2*>(res + (size_t)m1 * Ndim + n);
                float2 r2 = *reinterpret_cast<const float2*>(res + (size_t)m2 * Ndim + n);
                o1.x += r1.x; o1.y += r1.y;
                o2.x += r2.x; o2.y += r2.y;
                *reinterpret_cast<float2*>(C + (size_t)m1 * Ndim + n) = o1;
                *reinterpret_cast<float2*>(C + (size_t)m2 * Ndim + n) = o2;
            } else {
                // MODE 1: round + head-scatter (feeds attention)
                o1.x = roundtf(o1.x); o1.y = roundtf(o1.y);
                o2.x = roundtf(o2.x); o2.y = roundtf(o2.y);
                int h_ = n >> 6;
                int dd = n & (HEAD_DIM - 1);
                int b1_ = m1 >> 11, s1_ = m1 & (SEQ - 1);
                int b2_ = m2 >> 11, s2_ = m2 & (SEQ - 1);
                float* d1 = C + ((size_t)((b1_ * N_HEADS + h_) * SEQ + s1_)) * HEAD_DIM + dd;
                float* d2 = C + ((size_t)((b2_ * N_HEADS + h_) * SEQ + s2_)) * HEAD_DIM + dd;
                *reinterpret_cast<float2*>(d1) = o1;
                *reinterpret_cast<float2*>(d2) = o2;
            }
        }
    }
}

// ---------------------------------------------------------------------------
// Flash attention on tensor cores (tf32 mma). 128 q-rows/block, 8 warps;
// each warp owns 16 full q-rows (warp-local softmax state). Inputs are
// pre-rounded tf32 bits -> staging is raw copies (Q scale 0.125 exact).
// Output ctx: tf32-rounded, k-permuted (consumed by O-proj as A).
// ---------------------------------------------------------------------------
#define QS_ST 68   // %32==4
#define KS_ST 68
#define VS_ST 72   // %32==8
#define PS_ST 68
#define ATTN_SMEM ((128*QS_ST + 64*KS_ST + 64*VS_ST + 128*PS_ST) * 4)

__global__ __launch_bounds__(256) void attn_kernel(
    const float* __restrict__ Q, const float* __restrict__ K,
    const float* __restrict__ V, float* __restrict__ ctx)
{
    extern __shared__ unsigned smu[];
    unsigned* Qs = smu;
    unsigned* Ks = Qs + 128 * QS_ST;
    unsigned* Vs = Ks + 64 * KS_ST;
    unsigned* Ps = Vs + 64 * VS_ST;

    int bh   = blockIdx.y;
    int q0   = blockIdx.x * 128;
    int tid  = threadIdx.x;
    int lane = tid & 31;
    int warp = tid >> 5;
    int g    = lane >> 2;
    int tg   = lane & 3;
    int r0   = warp * 16 + g;

    const float* Qg = Q + ((size_t)bh * SEQ + q0) * HEAD_DIM;
    const float* Kg = K + (size_t)bh * SEQ * HEAD_DIM;
    const float* Vg = V + (size_t)bh * SEQ * HEAD_DIM;

    #pragma unroll
    for (int p = 0; p < 8; p++) {
        int f = tid + p * 256, r = f >> 4, c = (f & 15) * 4;
        float4 v = *reinterpret_cast<const float4*>(Qg + (size_t)r * HEAD_DIM + c);
        Qs[r * QS_ST + c + 0] = __float_as_uint(v.x * 0.125f);
        Qs[r * QS_ST + c + 1] = __float_as_uint(v.y * 0.125f);
        Qs[r * QS_ST + c + 2] = __float_as_uint(v.z * 0.125f);
        Qs[r * QS_ST + c + 3] = __float_as_uint(v.w * 0.125f);
    }

    float m[2] = {-1e30f, -1e30f};
    float l[2] = {0.f, 0.f};
    float acc[8][4] = {};

    for (int kt = 0; kt < SEQ; kt += 64) {
        __syncthreads();
        #pragma unroll
        for (int p = 0; p < 4; p++) {
            int f = tid + p * 256, r = f >> 4, c = (f & 15) * 4;
            uint4 kv = *reinterpret_cast<const uint4*>(Kg + (size_t)(kt + r) * HEAD_DIM + c);
            Ks[r * KS_ST + c + 0] = kv.x;
            Ks[r * KS_ST + c + 1] = kv.y;
            Ks[r * KS_ST + c + 2] = kv.z;
            Ks[r * KS_ST + c + 3] = kv.w;
            uint4 vv = *reinterpret_cast<const uint4*>(Vg + (size_t)(kt + r) * HEAD_DIM + c);
            Vs[r * VS_ST + c + 0] = vv.x;
            Vs[r * VS_ST + c + 1] = vv.y;
            Vs[r * VS_ST + c + 2] = vv.z;
            Vs[r * VS_ST + c + 3] = vv.w;
        }
        __syncthreads();

        float s[8][4] = {};
        #pragma unroll
        for (int k8 = 0; k8 < 8; k8++) {
            int k0 = k8 * 8;
            unsigned aq[4];
            aq[0] = Qs[r0 * QS_ST + k0 + tg];
            aq[1] = Qs[(r0 + 8) * QS_ST + k0 + tg];
            aq[2] = Qs[r0 * QS_ST + k0 + tg + 4];
            aq[3] = Qs[(r0 + 8) * QS_ST + k0 + tg + 4];
            #pragma unroll
            for (int nt = 0; nt < 8; nt++) {
                int n = nt * 8 + g;
                unsigned bk[2];
                bk[0] = Ks[n * KS_ST + k0 + tg];
                bk[1] = Ks[n * KS_ST + k0 + tg + 4];
                mma_tf32(s[nt], aq, bk);
            }
        }

        #pragma unroll
        for (int h2 = 0; h2 < 2; h2++) {
            float mx = -1e30f;
            #pragma unroll
            for (int nt = 0; nt < 8; nt++)
                mx = fmaxf(mx, fmaxf(s[nt][h2 * 2], s[nt][h2 * 2 + 1]));
            mx = fmaxf(mx, __shfl_xor_sync(0xffffffffu, mx, 1));
            mx = fmaxf(mx, __shfl_xor_sync(0xffffffffu, mx, 2));
            float mnew = fmaxf(m[h2], mx);
            float corr = __expf(m[h2] - mnew);
            m[h2] = mnew;
            int row = warp * 16 + h2 * 8 + g;
            float rs = 0.f;
            #pragma unroll
            for (int nt = 0; nt < 8; nt++) {
                float e0 = __expf(s[nt][h2 * 2]     - mnew);
                float e1 = __expf(s[nt][h2 * 2 + 1] - mnew);
                rs += e0 + e1;
                int cc = nt * 8 + 2 * tg;
                Ps[row * PS_ST + cc]     = f2tf32(e0);
                Ps[row * PS_ST + cc + 1] = f2tf32(e1);
            }
            rs += __shfl_xor_sync(0xffffffffu, rs, 1);
            rs += __shfl_xor_sync(0xffffffffu, rs, 2);
            l[h2] = l[h2] * corr + rs;
            #pragma unroll
            for (int nt = 0; nt < 8; nt++) {
                acc[nt][h2 * 2]     *= corr;
                acc[nt][h2 * 2 + 1] *= corr;
            }
        }
        __syncwarp();

        #pragma unroll
        for (int k8 = 0; k8 < 8; k8++) {
            int k0 = k8 * 8;
            unsigned ap[4];
            ap[0] = Ps[r0 * PS_ST + k0 + tg];
            ap[1] = Ps[(r0 + 8) * PS_ST + k0 + tg];
            ap[2] = Ps[r0 * PS_ST + k0 + tg + 4];
            ap[3] = Ps[(r0 + 8) * PS_ST + k0 + tg + 4];
            #pragma unroll
            for (int nt = 0; nt < 8; nt++) {
                int n = nt * 8 + g;
                unsigned bv[2];
                bv[0] = Vs[(k0 + tg) * VS_ST + n];
                bv[1] = Vs[(k0 + tg + 4) * VS_ST + n];
                mma_tf32(acc[nt], ap, bv);
            }
        }
    }

    // write ctx[b, s, h*64+d] rounded + k-permuted (O-proj A input)
    int b_ = bh >> 4, h_ = bh & 15;
    #pragma unroll
    for (int h2 = 0; h2 < 2; h2++) {
        int row   = q0 + warp * 16 + h2 * 8 + g;
        float inv = 1.0f / l[h2];
        float* dst = ctx + ((size_t)(b_ * SEQ + row)) * D_MODEL;
        #pragma unroll
        for (int nt = 0; nt < 8; nt++) {
            int c0 = h_ * HEAD_DIM + nt * 8 + 2 * tg;
            dst[kperm(c0)]     = roundtf(acc[nt][h2 * 2]     * inv);
            dst[kperm(c0 + 1)] = roundtf(acc[nt][h2 * 2 + 1] * inv);
        }
    }
}

// ---------------------------------------------------------------------------
// Launch
// ---------------------------------------------------------------------------
extern "C" void kernel_launch(void* const* d_in, const int* in_sizes, int n_in,
                              void* d_out, int out_size)
{
    const float* x   = (const float*)d_in[0];
    const float* wq  = (const float*)d_in[1];
    const float* bq  = (const float*)d_in[2];
    const float* wk  = (const float*)d_in[3];
    const float* bk  = (const float*)d_in[4];
    const float* wv  = (const float*)d_in[5];
    const float* bv  = (const float*)d_in[6];
    const float* wo  = (const float*)d_in[7];
    const float* bo  = (const float*)d_in[8];
    const float* w1  = (const float*)d_in[9];
    const float* b1  = (const float*)d_in[10];
    const float* w2  = (const float*)d_in[11];
    const float* b2  = (const float*)d_in[12];
    const float* g1  = (const float*)d_in[13];
    const float* be1 = (const float*)d_in[14];
    const float* g2  = (const float*)d_in[15];
    const float* be2 = (const float*)d_in[16];
    float* out = (float*)d_out;

    float *nx, *q, *k, *v, *ctx, *x2, *nx2, *ffh;
    float *wqt, *wkt, *wvt, *wot, *w1t, *w2t;
    cudaGetSymbolAddress((void**)&nx,  g_nx);
    cudaGetSymbolAddress((void**)&q,   g_q);
    cudaGetSymbolAddress((void**)&k,   g_k);
    cudaGetSymbolAddress((void**)&v,   g_v);
    cudaGetSymbolAddress((void**)&ctx, g_ctx);
    cudaGetSymbolAddress((void**)&x2,  g_x2);
    cudaGetSymbolAddress((void**)&nx2, g_nx2);
    cudaGetSymbolAddress((void**)&ffh, g_ffh);
    cudaGetSymbolAddress((void**)&wqt, g_wqt);
    cudaGetSymbolAddress((void**)&wkt, g_wkt);
    cudaGetSymbolAddress((void**)&wvt, g_wvt);
    cudaGetSymbolAddress((void**)&wot, g_wot);
    cudaGetSymbolAddress((void**)&w1t, g_w1t);
    cudaGetSymbolAddress((void**)&w2t, g_w2t);

    cudaFuncSetAttribute(mmagemm_kernel<1>,
                         cudaFuncAttributeMaxDynamicSharedMemorySize, GEMM_SMEM);
    cudaFuncSetAttribute(mmagemm_kernel<2>,
                         cudaFuncAttributeMaxDynamicSharedMemorySize, GEMM_SMEM);
    cudaFuncSetAttribute(mmagemm_kernel<3>,
                         cudaFuncAttributeMaxDynamicSharedMemorySize, GEMM_SMEM);
    cudaFuncSetAttribute(attn_kernel,
                         cudaFuncAttributeMaxDynamicSharedMemorySize, ATTN_SMEM);

    // weight prep (transpose + tf32 round + k-permute)
    wprep_kernel<<<dim3(D_MODEL/32, D_MODEL/32), 256>>>(wq, wqt, D_MODEL, D_MODEL);
    wprep_kernel<<<dim3(D_MODEL/32, D_MODEL/32), 256>>>(wk, wkt, D_MODEL, D_MODEL);
    wprep_kernel<<<dim3(D_MODEL/32, D_MODEL/32), 256>>>(wv, wvt, D_MODEL, D_MODEL);
    wprep_kernel<<<dim3(D_MODEL/32, D_MODEL/32), 256>>>(wo, wot, D_MODEL, D_MODEL);
    wprep_kernel<<<dim3(D_FF/32,    D_MODEL/32), 256>>>(w1, w1t, D_MODEL, D_FF);
    wprep_kernel<<<dim3(D_MODEL/32, D_FF/32),    256>>>(w2, w2t, D_FF, D_MODEL);

    dim3 gD (D_MODEL / BN, M_ROWS / BM);   // (8, 32)
    dim3 gFF(D_FF   / BN, M_ROWS / BM);    // (32, 32)

    ln_kernel<<<M_ROWS, 256>>>(x, g1, be1, nx);
    mmagemm_kernel<1><<<gD, 256, GEMM_SMEM>>>(nx, wqt, bq, nullptr, q, D_MODEL, D_MODEL);
    mmagemm_kernel<1><<<gD, 256, GEMM_SMEM>>>(nx, wkt, bk, nullptr, k, D_MODEL, D_MODEL);
    mmagemm_kernel<1><<<gD, 256, GEMM_SMEM>>>(nx, wvt, bv, nullptr, v, D_MODEL, D_MODEL);
    attn_kernel<<<dim3(SEQ / 128, BATCH * N_HEADS), 256, ATTN_SMEM>>>(q, k, v, ctx);
    mmagemm_kernel<3><<<gD, 256, GEMM_SMEM>>>(ctx, wot, bo, x, x2, D_MODEL, D_MODEL);
    ln_kernel<<<M_ROWS, 256>>>(x2, g2, be2, nx2);
    mmagemm_kernel<2><<<gFF, 256, GEMM_SMEM>>>(nx2, w1t, b1, nullptr, ffh, D_FF, D_MODEL);
    mmagemm_kernel<3><<<gD, 256, GEMM_SMEM>>>(ffh, w2t, b2, x2, out, D_MODEL, D_FF);
}

// round 10
// speedup vs baseline: 1.0312x; 1.0312x over previous
#include <cuda_runtime.h>
#include <math.h>

#define D_MODEL   1024
#define N_HEADS   16
#define HEAD_DIM  64
#define D_FF      4096
#define SEQ       2048
#define BATCH     2
#define M_ROWS    (BATCH * SEQ)   // 4096
#define EPS       1e-5f

// ---------------------------------------------------------------------------
// Scratch (device globals -- no allocations allowed)
// ---------------------------------------------------------------------------
__device__ float g_nx [M_ROWS * D_MODEL];   // LN1 out (tf32-rounded)
__device__ float g_q  [M_ROWS * D_MODEL];   // [B,H,S,d] (tf32-rounded)
__device__ float g_k  [M_ROWS * D_MODEL];
__device__ float g_v  [M_ROWS * D_MODEL];
__device__ float g_ctx[M_ROWS * D_MODEL];   // [B,S,D] (tf32-rounded)
__device__ float g_x2 [M_ROWS * D_MODEL];   // fp32 exact
__device__ float g_nx2[M_ROWS * D_MODEL];   // (tf32-rounded)
__device__ float g_ffh[M_ROWS * D_FF];      // (tf32-rounded)
// tf32-rounded weight copies (same [K][N] layout as originals)
__device__ float g_wqr[D_MODEL * D_MODEL];
__device__ float g_wkr[D_MODEL * D_MODEL];
__device__ float g_wvr[D_MODEL * D_MODEL];
__device__ float g_wor[D_MODEL * D_MODEL];
__device__ float g_w1r[D_MODEL * D_FF];
__device__ float g_w2r[D_FF * D_MODEL];

__device__ __forceinline__ unsigned f2tf32(float x) {
    unsigned y;
    asm("cvt.rna.tf32.f32 %0, %1;" : "=r"(y) : "f"(x));
    return y;
}
__device__ __forceinline__ float roundtf(float x) {
    return __uint_as_float(f2tf32(x));
}

__device__ __forceinline__ void mma_tf32(float* c, const unsigned* a, const unsigned* b) {
    asm volatile(
        "mma.sync.aligned.m16n8k8.row.col.f32.tf32.tf32.f32 "
        "{%0,%1,%2,%3}, {%4,%5,%6,%7}, {%8,%9}, {%0,%1,%2,%3};"
        : "+f"(c[0]), "+f"(c[1]), "+f"(c[2]), "+f"(c[3])
        : "r"(a[0]), "r"(a[1]), "r"(a[2]), "r"(a[3]),
          "r"(b[0]), "r"(b[1]));
}

#define CP_ASYNC16(dst, src) \
    asm volatile("cp.async.cg.shared.global [%0], [%1], 16;" :: "r"(dst), "l"(src))

// ---------------------------------------------------------------------------
// Weight rounding: streaming copy, float4 per thread
// ---------------------------------------------------------------------------
__global__ __launch_bounds__(256) void wround_kernel(
    const float* __restrict__ w, float* __restrict__ o, int n4)
{
    int i = blockIdx.x * 256 + threadIdx.x;
    if (i < n4) {
        float4 v = reinterpret_cast<const float4*>(w)[i];
        v.x = roundtf(v.x); v.y = roundtf(v.y);
        v.z = roundtf(v.z); v.w = roundtf(v.w);
        reinterpret_cast<float4*>(o)[i] = v;
    }
}

// ---------------------------------------------------------------------------
// LayerNorm -> tf32-rounded output (consumed as GEMM A)
// ---------------------------------------------------------------------------
__global__ __launch_bounds__(256) void ln_kernel(
    const float* __restrict__ x, const float* __restrict__ g,
    const float* __restrict__ b, float* __restrict__ out)
{
    int row = blockIdx.x;
    int t   = threadIdx.x;
    const float4* xr = reinterpret_cast<const float4*>(x + (size_t)row * D_MODEL);
    float4 v = xr[t];
    float s  = v.x + v.y + v.z + v.w;
    float ss = v.x * v.x + v.y * v.y + v.z * v.z + v.w * v.w;
    #pragma unroll
    for (int o = 16; o > 0; o >>= 1) {
        s  += __shfl_xor_sync(0xffffffffu, s,  o);
        ss += __shfl_xor_sync(0xffffffffu, ss, o);
    }
    __shared__ float shs[8], shss[8];
    int w = t >> 5;
    if ((t & 31) == 0) { shs[w] = s; shss[w] = ss; }
    __syncthreads();
    float tot = 0.f, tot2 = 0.f;
    #pragma unroll
    for (int i = 0; i < 8; i++) { tot += shs[i]; tot2 += shss[i]; }
    float mu  = tot * (1.0f / D_MODEL);
    float var = tot2 * (1.0f / D_MODEL) - mu * mu;
    float inv = rsqrtf(var + EPS);
    float4 gv = reinterpret_cast<const float4*>(g)[t];
    float4 bv = reinterpret_cast<const float4*>(b)[t];
    float4 o;
    o.x = roundtf((v.x - mu) * inv * gv.x + bv.x);
    o.y = roundtf((v.y - mu) * inv * gv.y + bv.y);
    o.z = roundtf((v.z - mu) * inv * gv.z + bv.z);
    o.w = roundtf((v.w - mu) * inv * gv.w + bv.w);
    reinterpret_cast<float4*>(out + (size_t)row * D_MODEL)[t] = o;
}

// ---------------------------------------------------------------------------
// TF32 GEMM: 128x128x32 tile, 8 warps (warp tile 64x32), cp.async double
// buffer. Inputs pre-rounded to tf32 -> no cvt in the mainloop.
// A: MxK row-major, B: KxN row-major (both tf32-valued fp32).
// MODE 1: round(acc+bias) head-scatter; 2: round(relu(acc+bias));
// MODE 3: acc + bias + res (fp32 exact).
// ---------------------------------------------------------------------------
#define BM 128
#define BN 128
#define BK 32
#define AS_ST 36    // bank = 4g+tg -> conflict-free scalar frag loads
#define BS_ST 136   // bank = 8tg+(8nt+g) -> conflict-free
#define GEMM_SMEM ((2*BM*AS_ST + 2*BK*BS_ST) * 4)

template<int MODE>
__global__ __launch_bounds__(256) void mmagemm_kernel(
    const float* __restrict__ A, const float* __restrict__ B,
    const float* __restrict__ bias, const float* __restrict__ res,
    float* __restrict__ C, int Ndim, int Kdim)
{
    extern __shared__ float smf[];
    float* As = smf;                       // [2][BM][AS_ST]  ([m][k])
    float* Bs = smf + 2 * BM * AS_ST;      // [2][BK][BS_ST]  ([k][n])

    int tid  = threadIdx.x;
    int lane = tid & 31;
    int warp = tid >> 5;
    int wm   = warp >> 2;
    int wn   = warp & 3;
    int g    = lane >> 2;
    int tg   = lane & 3;
    int row0 = blockIdx.y * BM;
    int col0 = blockIdx.x * BN;

    float acc[4][4][4] = {};

    auto issue_stage = [&](int kb, int buf) {
        float* Ab = As + buf * BM * AS_ST;
        float* Bb = Bs + buf * BK * BS_ST;
        #pragma unroll
        for (int p = 0; p < 4; p++) {
            int f = tid + p * 256, r = f >> 3, k4 = (f & 7) * 4;
            unsigned d = (unsigned)__cvta_generic_to_shared(Ab + r * AS_ST + k4);
            CP_ASYNC16(d, A + (size_t)(row0 + r) * Kdim + kb + k4);
        }
        #pragma unroll
        for (int p = 0; p < 4; p++) {
            int f = tid + p * 256, kk = f >> 5, n4 = (f & 31) * 4;
            unsigned d = (unsigned)__cvta_generic_to_shared(Bb + kk * BS_ST + n4);
            CP_ASYNC16(d, B + (size_t)(kb + kk) * Ndim + col0 + n4);
        }
        asm volatile("cp.async.commit_group;");
    };

    issue_stage(0, 0);
    int nk = Kdim / BK;
    for (int t = 0; t < nk; t++) {
        int buf = t & 1;
        if (t + 1 < nk) {
            issue_stage((t + 1) * BK, buf ^ 1);
            asm volatile("cp.async.wait_group 1;");
        } else {
            asm volatile("cp.async.wait_group 0;");
        }
        __syncthreads();
        const unsigned* Ab = reinterpret_cast<const unsigned*>(As + buf * BM * AS_ST);
        const unsigned* Bb = reinterpret_cast<const unsigned*>(Bs + buf * BK * BS_ST);
        #pragma unroll
        for (int s = 0; s < 4; s++) {
            int k0 = s * 8;
            unsigned af[4][4];
            #pragma unroll
            for (int mt = 0; mt < 4; mt++) {
                int r = wm * 64 + mt * 16 + g;
                af[mt][0] = Ab[r * AS_ST + k0 + tg];
                af[mt][1] = Ab[(r + 8) * AS_ST + k0 + tg];
                af[mt][2] = Ab[r * AS_ST + k0 + tg + 4];
                af[mt][3] = Ab[(r + 8) * AS_ST + k0 + tg + 4];
            }
            unsigned bf[4][2];
            #pragma unroll
            for (int nt = 0; nt < 4; nt++) {
                int n = wn * 32 + nt * 8 + g;
                bf[nt][0] = Bb[(k0 + tg) * BS_ST + n];
                bf[nt][1] = Bb[(k0 + tg + 4) * BS_ST + n];
            }
            #pragma unroll
            for (int mt = 0; mt < 4; mt++)
                #pragma unroll
                for (int nt = 0; nt < 4; nt++)
                    mma_tf32(acc[mt][nt], af[mt], bf[nt]);
        }
        __syncthreads();
    }

    #pragma unroll
    for (int mt = 0; mt < 4; mt++) {
        int m1 = row0 + wm * 64 + mt * 16 + g;
        int m2 = m1 + 8;
        #pragma unroll
        for (int nt = 0; nt < 4; nt++) {
            int n = col0 + wn * 32 + nt * 8 + 2 * tg;
            float2 bb = *reinterpret_cast<const float2*>(bias + n);
            float2 o1, o2;
            o1.x = acc[mt][nt][0] + bb.x;
            o1.y = acc[mt][nt][1] + bb.y;
            o2.x = acc[mt][nt][2] + bb.x;
            o2.y = acc[mt][nt][3] + bb.y;
            if (MODE == 2) {
                o1.x = roundtf(fmaxf(o1.x, 0.f)); o1.y = roundtf(fmaxf(o1.y, 0.f));
                o2.x = roundtf(fmaxf(o2.x, 0.f)); o2.y = roundtf(fmaxf(o2.y, 0.f));
            }
            if (MODE == 3) {
                float2 r1 = *reinterpret_cast<const float2*>(res + (size_t)m1 * Ndim + n);
                float2 r2 = *reinterpret_cast<const float2*>(res + (size_t)m2 * Ndim + n);
                o1.x += r1.x; o1.y += r1.y;
                o2.x += r2.x; o2.y += r2.y;
            }
            if (MODE == 1) {
                o1.x = roundtf(o1.x); o1.y = roundtf(o1.y);
                o2.x = roundtf(o2.x); o2.y = roundtf(o2.y);
                int h_ = n >> 6;
                int dd = n & (HEAD_DIM - 1);
                int b1_ = m1 >> 11, s1_ = m1 & (SEQ - 1);
                int b2_ = m2 >> 11, s2_ = m2 & (SEQ - 1);
                float* d1 = C + ((size_t)((b1_ * N_HEADS + h_) * SEQ + s1_)) * HEAD_DIM + dd;
                float* d2 = C + ((size_t)((b2_ * N_HEADS + h_) * SEQ + s2_)) * HEAD_DIM + dd;
                *reinterpret_cast<float2*>(d1) = o1;
                *reinterpret_cast<float2*>(d2) = o2;
            } else {
                *reinterpret_cast<float2*>(C + (size_t)m1 * Ndim + n) = o1;
                *reinterpret_cast<float2*>(C + (size_t)m2 * Ndim + n) = o2;
            }
        }
    }
}

// ---------------------------------------------------------------------------
// Flash attention on tensor cores (tf32 mma). 128 q-rows/block, 8 warps;
// each warp owns 16 full q-rows (warp-local softmax). Inputs pre-rounded
// -> staging is raw copies (Q x0.125 exact). ctx written tf32-rounded.
// ---------------------------------------------------------------------------
#define QS_ST 68   // %32==4
#define KS_ST 68
#define VS_ST 72   // %32==8
#define PS_ST 68
#define ATTN_SMEM ((128*QS_ST + 64*KS_ST + 64*VS_ST + 128*PS_ST) * 4)

__global__ __launch_bounds__(256) void attn_kernel(
    const float* __restrict__ Q, const float* __restrict__ K,
    const float* __restrict__ V, float* __restrict__ ctx)
{
    extern __shared__ unsigned smu[];
    unsigned* Qs = smu;
    unsigned* Ks = Qs + 128 * QS_ST;
    unsigned* Vs = Ks + 64 * KS_ST;
    unsigned* Ps = Vs + 64 * VS_ST;

    int bh   = blockIdx.y;
    int q0   = blockIdx.x * 128;
    int tid  = threadIdx.x;
    int lane = tid & 31;
    int warp = tid >> 5;
    int g    = lane >> 2;
    int tg   = lane & 3;
    int r0   = warp * 16 + g;

    const float* Qg = Q + ((size_t)bh * SEQ + q0) * HEAD_DIM;
    const float* Kg = K + (size_t)bh * SEQ * HEAD_DIM;
    const float* Vg = V + (size_t)bh * SEQ * HEAD_DIM;

    #pragma unroll
    for (int p = 0; p < 8; p++) {
        int f = tid + p * 256, r = f >> 4, c = (f & 15) * 4;
        float4 v = *reinterpret_cast<const float4*>(Qg + (size_t)r * HEAD_DIM + c);
        Qs[r * QS_ST + c + 0] = __float_as_uint(v.x * 0.125f);
        Qs[r * QS_ST + c + 1] = __float_as_uint(v.y * 0.125f);
        Qs[r * QS_ST + c + 2] = __float_as_uint(v.z * 0.125f);
        Qs[r * QS_ST + c + 3] = __float_as_uint(v.w * 0.125f);
    }

    float m[2] = {-1e30f, -1e30f};
    float l[2] = {0.f, 0.f};
    float acc[8][4] = {};

    for (int kt = 0; kt < SEQ; kt += 64) {
        __syncthreads();
        #pragma unroll
        for (int p = 0; p < 4; p++) {
            int f = tid + p * 256, r = f >> 4, c = (f & 15) * 4;
            uint4 kv = *reinterpret_cast<const uint4*>(Kg + (size_t)(kt + r) * HEAD_DIM + c);
            Ks[r * KS_ST + c + 0] = kv.x;
            Ks[r * KS_ST + c + 1] = kv.y;
            Ks[r * KS_ST + c + 2] = kv.z;
            Ks[r * KS_ST + c + 3] = kv.w;
            uint4 vv = *reinterpret_cast<const uint4*>(Vg + (size_t)(kt + r) * HEAD_DIM + c);
            Vs[r * VS_ST + c + 0] = vv.x;
            Vs[r * VS_ST + c + 1] = vv.y;
            Vs[r * VS_ST + c + 2] = vv.z;
            Vs[r * VS_ST + c + 3] = vv.w;
        }
        __syncthreads();

        float s[8][4] = {};
        #pragma unroll
        for (int k8 = 0; k8 < 8; k8++) {
            int k0 = k8 * 8;
            unsigned aq[4];
            aq[0] = Qs[r0 * QS_ST + k0 + tg];
            aq[1] = Qs[(r0 + 8) * QS_ST + k0 + tg];
            aq[2] = Qs[r0 * QS_ST + k0 + tg + 4];
            aq[3] = Qs[(r0 + 8) * QS_ST + k0 + tg + 4];
            #pragma unroll
            for (int nt = 0; nt < 8; nt++) {
                int n = nt * 8 + g;
                unsigned bk[2];
                bk[0] = Ks[n * KS_ST + k0 + tg];
                bk[1] = Ks[n * KS_ST + k0 + tg + 4];
                mma_tf32(s[nt], aq, bk);
            }
        }

        #pragma unroll
        for (int h2 = 0; h2 < 2; h2++) {
            float mx = -1e30f;
            #pragma unroll
            for (int nt = 0; nt < 8; nt++)
                mx = fmaxf(mx, fmaxf(s[nt][h2 * 2], s[nt][h2 * 2 + 1]));
            mx = fmaxf(mx, __shfl_xor_sync(0xffffffffu, mx, 1));
            mx = fmaxf(mx, __shfl_xor_sync(0xffffffffu, mx, 2));
            float mnew = fmaxf(m[h2], mx);
            float corr = __expf(m[h2] - mnew);
            m[h2] = mnew;
            int row = warp * 16 + h2 * 8 + g;
            float rs = 0.f;
            #pragma unroll
            for (int nt = 0; nt < 8; nt++) {
                float e0 = __expf(s[nt][h2 * 2]     - mnew);
                float e1 = __expf(s[nt][h2 * 2 + 1] - mnew);
                rs += e0 + e1;
                int cc = nt * 8 + 2 * tg;
                Ps[row * PS_ST + cc]     = f2tf32(e0);
                Ps[row * PS_ST + cc + 1] = f2tf32(e1);
            }
            rs += __shfl_xor_sync(0xffffffffu, rs, 1);
            rs += __shfl_xor_sync(0xffffffffu, rs, 2);
            l[h2] = l[h2] * corr + rs;
            #pragma unroll
            for (int nt = 0; nt < 8; nt++) {
                acc[nt][h2 * 2]     *= corr;
                acc[nt][h2 * 2 + 1] *= corr;
            }
        }
        __syncwarp();

        #pragma unroll
        for (int k8 = 0; k8 < 8; k8++) {
            int k0 = k8 * 8;
            unsigned ap[4];
            ap[0] = Ps[r0 * PS_ST + k0 + tg];
            ap[1] = Ps[(r0 + 8) * PS_ST + k0 + tg];
            ap[2] = Ps[r0 * PS_ST + k0 + tg + 4];
            ap[3] = Ps[(r0 + 8) * PS_ST + k0 + tg + 4];
            #pragma unroll
            for (int nt = 0; nt < 8; nt++) {
                int n = nt * 8 + g;
                unsigned bv[2];
                bv[0] = Vs[(k0 + tg) * VS_ST + n];
                bv[1] = Vs[(k0 + tg + 4) * VS_ST + n];
                mma_tf32(acc[nt], ap, bv);
            }
        }
    }

    // write ctx[b, s, h*64+d] tf32-rounded (O-proj A input)
    int b_ = bh >> 4, h_ = bh & 15;
    #pragma unroll
    for (int h2 = 0; h2 < 2; h2++) {
        int row   = q0 + warp * 16 + h2 * 8 + g;
        float inv = 1.0f / l[h2];
        float* dst = ctx + ((size_t)(b_ * SEQ + row)) * D_MODEL + h_ * HEAD_DIM;
        #pragma unroll
        for (int nt = 0; nt < 8; nt++) {
            int cc = nt * 8 + 2 * tg;
            float2 o;
            o.x = roundtf(acc[nt][h2 * 2]     * inv);
            o.y = roundtf(acc[nt][h2 * 2 + 1] * inv);
            *reinterpret_cast<float2*>(dst + cc) = o;
        }
    }
}

// ---------------------------------------------------------------------------
// Launch
// ---------------------------------------------------------------------------
extern "C" void kernel_launch(void* const* d_in, const int* in_sizes, int n_in,
                              void* d_out, int out_size)
{
    const float* x   = (const float*)d_in[0];
    const float* wq  = (const float*)d_in[1];
    const float* bq  = (const float*)d_in[2];
    const float* wk  = (const float*)d_in[3];
    const float* bk  = (const float*)d_in[4];
    const float* wv  = (const float*)d_in[5];
    const float* bv  = (const float*)d_in[6];
    const float* wo  = (const float*)d_in[7];
    const float* bo  = (const float*)d_in[8];
    const float* w1  = (const float*)d_in[9];
    const float* b1  = (const float*)d_in[10];
    const float* w2  = (const float*)d_in[11];
    const float* b2  = (const float*)d_in[12];
    const float* g1  = (const float*)d_in[13];
    const float* be1 = (const float*)d_in[14];
    const float* g2  = (const float*)d_in[15];
    const float* be2 = (const float*)d_in[16];
    float* out = (float*)d_out;

    float *nx, *q, *k, *v, *ctx, *x2, *nx2, *ffh;
    float *wqr, *wkr, *wvr, *wor, *w1r, *w2r;
    cudaGetSymbolAddress((void**)&nx,  g_nx);
    cudaGetSymbolAddress((void**)&q,   g_q);
    cudaGetSymbolAddress((void**)&k,   g_k);
    cudaGetSymbolAddress((void**)&v,   g_v);
    cudaGetSymbolAddress((void**)&ctx, g_ctx);
    cudaGetSymbolAddress((void**)&x2,  g_x2);
    cudaGetSymbolAddress((void**)&nx2, g_nx2);
    cudaGetSymbolAddress((void**)&ffh, g_ffh);
    cudaGetSymbolAddress((void**)&wqr, g_wqr);
    cudaGetSymbolAddress((void**)&wkr, g_wkr);
    cudaGetSymbolAddress((void**)&wvr, g_wvr);
    cudaGetSymbolAddress((void**)&wor, g_wor);
    cudaGetSymbolAddress((void**)&w1r, g_w1r);
    cudaGetSymbolAddress((void**)&w2r, g_w2r);

    cudaFuncSetAttribute(mmagemm_kernel<1>,
                         cudaFuncAttributeMaxDynamicSharedMemorySize, GEMM_SMEM);
    cudaFuncSetAttribute(mmagemm_kernel<2>,
                         cudaFuncAttributeMaxDynamicSharedMemorySize, GEMM_SMEM);
    cudaFuncSetAttribute(mmagemm_kernel<3>,
                         cudaFuncAttributeMaxDynamicSharedMemorySize, GEMM_SMEM);
    cudaFuncSetAttribute(attn_kernel,
                         cudaFuncAttributeMaxDynamicSharedMemorySize, ATTN_SMEM);

    // weight rounding (streaming copies)
    int nDD4 = D_MODEL * D_MODEL / 4;
    int nDF4 = D_MODEL * D_FF / 4;
    wround_kernel<<<(nDD4 + 255) / 256, 256>>>(wq, wqr, nDD4);
    wround_kernel<<<(nDD4 + 255) / 256, 256>>>(wk, wkr, nDD4);
    wround_kernel<<<(nDD4 + 255) / 256, 256>>>(wv, wvr, nDD4);
    wround_kernel<<<(nDD4 + 255) / 256, 256>>>(wo, wor, nDD4);
    wround_kernel<<<(nDF4 + 255) / 256, 256>>>(w1, w1r, nDF4);
    wround_kernel<<<(nDF4 + 255) / 256, 256>>>(w2, w2r, nDF4);

    dim3 gD (D_MODEL / BN, M_ROWS / BM);   // (8, 32)
    dim3 gFF(D_FF   / BN, M_ROWS / BM);    // (32, 32)

    ln_kernel<<<M_ROWS, 256>>>(x, g1, be1, nx);
    mmagemm_kernel<1><<<gD, 256, GEMM_SMEM>>>(nx, wqr, bq, nullptr, q, D_MODEL, D_MODEL);
    mmagemm_kernel<1><<<gD, 256, GEMM_SMEM>>>(nx, wkr, bk, nullptr, k, D_MODEL, D_MODEL);
    mmagemm_kernel<1><<<gD, 256, GEMM_SMEM>>>(nx, wvr, bv, nullptr, v, D_MODEL, D_MODEL);
    attn_kernel<<<dim3(SEQ / 128, BATCH * N_HEADS), 256, ATTN_SMEM>>>(q, k, v, ctx);
    mmagemm_kernel<3><<<gD, 256, GEMM_SMEM>>>(ctx, wor, bo, x, x2, D_MODEL, D_MODEL);
    ln_kernel<<<M_ROWS, 256>>>(x2, g2, be2, nx2);
    mmagemm_kernel<2><<<gFF, 256, GEMM_SMEM>>>(nx2, w1r, b1, nullptr, ffh, D_FF, D_MODEL);
    mmagemm_kernel<3><<<gD, 256, GEMM_SMEM>>>(ffh, w2r, b2, x2, out, D_MODEL, D_FF);
}

// round 12
// speedup vs baseline: 1.2225x; 1.1855x over previous
#include <cuda_runtime.h>
#include <math.h>

#define D_MODEL   1024
#define N_HEADS   16
#define HEAD_DIM  64
#define D_FF      4096
#define SEQ       2048
#define BATCH     2
#define M_ROWS    (BATCH * SEQ)   // 4096
#define EPS       1e-5f

// ---------------------------------------------------------------------------
// Scratch (device globals -- no allocations allowed)
// ---------------------------------------------------------------------------
__device__ float g_nx  [M_ROWS * D_MODEL];   // LN1 out (tf32-rounded)
__device__ float g_q   [M_ROWS * D_MODEL];   // [B,H,S,d]
__device__ float g_k   [M_ROWS * D_MODEL];   // [B,H,S,d]
__device__ float g_vt  [M_ROWS * D_MODEL];   // [B,H,d,S]  (transposed V)
__device__ float g_ctx [M_ROWS * D_MODEL];   // [B,S,D] (tf32-rounded)
__device__ float g_x2  [M_ROWS * D_MODEL];   // fp32 exact
__device__ float g_nx2 [M_ROWS * D_MODEL];   // tf32-rounded
__device__ float g_ffh [M_ROWS * D_FF];      // tf32-rounded
__device__ float g_wqkv[D_MODEL * 3 * D_MODEL];  // [K][3N] tf32-rounded
__device__ float g_bqkv[3 * D_MODEL];
__device__ float g_wor [D_MODEL * D_MODEL];
__device__ float g_w1r [D_MODEL * D_FF];
__device__ float g_w2r [D_FF * D_MODEL];

__device__ __forceinline__ unsigned f2tf32(float x) {
    unsigned y;
    asm("cvt.rna.tf32.f32 %0, %1;" : "=r"(y) : "f"(x));
    return y;
}
__device__ __forceinline__ float roundtf(float x) {
    return __uint_as_float(f2tf32(x));
}
// pack two f32 -> bf16x2 (lo in lower half, hi in upper half)
__device__ __forceinline__ unsigned packbf(float lo, float hi) {
    unsigned r;
    asm("cvt.rn.satfinite.bf16x2.f32 %0, %1, %2;" : "=r"(r) : "f"(hi), "f"(lo));
    return r;
}

__device__ __forceinline__ void mma_tf32(float* c, const unsigned* a, const unsigned* b) {
    asm volatile(
        "mma.sync.aligned.m16n8k8.row.col.f32.tf32.tf32.f32 "
        "{%0,%1,%2,%3}, {%4,%5,%6,%7}, {%8,%9}, {%0,%1,%2,%3};"
        : "+f"(c[0]), "+f"(c[1]), "+f"(c[2]), "+f"(c[3])
        : "r"(a[0]), "r"(a[1]), "r"(a[2]), "r"(a[3]),
          "r"(b[0]), "r"(b[1]));
}
__device__ __forceinline__ void mma_bf16(float* c, const unsigned* a, const unsigned* b) {
    asm volatile(
        "mma.sync.aligned.m16n8k16.row.col.f32.bf16.bf16.f32 "
        "{%0,%1,%2,%3}, {%4,%5,%6,%7}, {%8,%9}, {%0,%1,%2,%3};"
        : "+f"(c[0]), "+f"(c[1]), "+f"(c[2]), "+f"(c[3])
        : "r"(a[0]), "r"(a[1]), "r"(a[2]), "r"(a[3]),
          "r"(b[0]), "r"(b[1]));
}

#define CP_ASYNC16(dst, src) \
    asm volatile("cp.async.cg.shared.global [%0], [%1], 16;" :: "r"(dst), "l"(src))

// ---------------------------------------------------------------------------
// Weight prep
// ---------------------------------------------------------------------------
// round + copy into strided destination (row stride 3072) -- for QKV concat
__global__ __launch_bounds__(256) void wcat_kernel(
    const float* __restrict__ w, float* __restrict__ dst)
{
    int i  = blockIdx.x * 256 + threadIdx.x;      // over 1024*256 float4s
    int k  = i >> 8;
    int n4 = (i & 255) * 4;
    float4 v = reinterpret_cast<const float4*>(w)[i];
    v.x = roundtf(v.x); v.y = roundtf(v.y);
    v.z = roundtf(v.z); v.w = roundtf(v.w);
    *reinterpret_cast<float4*>(dst + (size_t)k * (3 * D_MODEL) + n4) = v;
}
__global__ __launch_bounds__(256) void wround_kernel(
    const float* __restrict__ w, float* __restrict__ o, int n4)
{
    int i = blockIdx.x * 256 + threadIdx.x;
    if (i < n4) {
        float4 v = reinterpret_cast<const float4*>(w)[i];
        v.x = roundtf(v.x); v.y = roundtf(v.y);
        v.z = roundtf(v.z); v.w = roundtf(v.w);
        reinterpret_cast<float4*>(o)[i] = v;
    }
}
__global__ __launch_bounds__(256) void bcat_kernel(
    const float* __restrict__ b0, const float* __restrict__ b1,
    const float* __restrict__ b2, float* __restrict__ dst)
{
    int i = blockIdx.x * 256 + threadIdx.x;    // 0..767, float4
    int n = i * 4;
    const float* src = (n < 1024) ? b0 : (n < 2048) ? b1 : b2;
    reinterpret_cast<float4*>(dst)[i] =
        reinterpret_cast<const float4*>(src)[i & 255];
}

// ---------------------------------------------------------------------------
// LayerNorm -> tf32-rounded output
// ---------------------------------------------------------------------------
__global__ __launch_bounds__(256) void ln_kernel(
    const float* __restrict__ x, const float* __restrict__ g,
    const float* __restrict__ b, float* __restrict__ out)
{
    int row = blockIdx.x;
    int t   = threadIdx.x;
    const float4* xr = reinterpret_cast<const float4*>(x + (size_t)row * D_MODEL);
    float4 v = xr[t];
    float s  = v.x + v.y + v.z + v.w;
    float ss = v.x * v.x + v.y * v.y + v.z * v.z + v.w * v.w;
    #pragma unroll
    for (int o = 16; o > 0; o >>= 1) {
        s  += __shfl_xor_sync(0xffffffffu, s,  o);
        ss += __shfl_xor_sync(0xffffffffu, ss, o);
    }
    __shared__ float shs[8], shss[8];
    int w = t >> 5;
    if ((t & 31) == 0) { shs[w] = s; shss[w] = ss; }
    __syncthreads();
    float tot = 0.f, tot2 = 0.f;
    #pragma unroll
    for (int i = 0; i < 8; i++) { tot += shs[i]; tot2 += shss[i]; }
    float mu  = tot * (1.0f / D_MODEL);
    float var = tot2 * (1.0f / D_MODEL) - mu * mu;
    float inv = rsqrtf(var + EPS);
    float4 gv = reinterpret_cast<const float4*>(g)[t];
    float4 bv = reinterpret_cast<const float4*>(b)[t];
    float4 o;
    o.x = roundtf((v.x - mu) * inv * gv.x + bv.x);
    o.y = roundtf((v.y - mu) * inv * gv.y + bv.y);
    o.z = roundtf((v.z - mu) * inv * gv.z + bv.z);
    o.w = roundtf((v.w - mu) * inv * gv.w + bv.w);
    reinterpret_cast<float4*>(out + (size_t)row * D_MODEL)[t] = o;
}

// ---------------------------------------------------------------------------
// TF32 GEMM (R8 structure). MODE 1: QKV epilogue (q/k head-scatter, v
// transposed scatter); 2: round(relu); 3: bias + residual (fp32).
// ---------------------------------------------------------------------------
#define BM 128
#define BN 128
#define BK 32
#define AS_ST 36
#define BS_ST 136
#define GEMM_SMEM ((2*BM*AS_ST + 2*BK*BS_ST) * 4)

template<int MODE>
__global__ __launch_bounds__(256) void mmagemm_kernel(
    const float* __restrict__ A, const float* __restrict__ B,
    const float* __restrict__ bias, const float* __restrict__ res,
    float* __restrict__ C, float* __restrict__ Ck, float* __restrict__ Cv,
    int Ndim, int Kdim)
{
    extern __shared__ float smf[];
    float* As = smf;
    float* Bs = smf + 2 * BM * AS_ST;

    int tid  = threadIdx.x;
    int lane = tid & 31;
    int warp = tid >> 5;
    int wm   = warp >> 2;
    int wn   = warp & 3;
    int g    = lane >> 2;
    int tg   = lane & 3;
    int row0 = blockIdx.y * BM;
    int col0 = blockIdx.x * BN;

    float acc[4][4][4] = {};

    auto issue_stage = [&](int kb, int buf) {
        float* Ab = As + buf * BM * AS_ST;
        float* Bb = Bs + buf * BK * BS_ST;
        #pragma unroll
        for (int p = 0; p < 4; p++) {
            int f = tid + p * 256, r = f >> 3, k4 = (f & 7) * 4;
            unsigned d = (unsigned)__cvta_generic_to_shared(Ab + r * AS_ST + k4);
            CP_ASYNC16(d, A + (size_t)(row0 + r) * Kdim + kb + k4);
        }
        #pragma unroll
        for (int p = 0; p < 4; p++) {
            int f = tid + p * 256, kk = f >> 5, n4 = (f & 31) * 4;
            unsigned d = (unsigned)__cvta_generic_to_shared(Bb + kk * BS_ST + n4);
            CP_ASYNC16(d, B + (size_t)(kb + kk) * Ndim + col0 + n4);
        }
        asm volatile("cp.async.commit_group;");
    };

    issue_stage(0, 0);
    int nk = Kdim / BK;
    for (int t = 0; t < nk; t++) {
        int buf = t & 1;
        if (t + 1 < nk) {
            issue_stage((t + 1) * BK, buf ^ 1);
            asm volatile("cp.async.wait_group 1;");
        } else {
            asm volatile("cp.async.wait_group 0;");
        }
        __syncthreads();
        const float* Ab = As + buf * BM * AS_ST;
        const float* Bb = Bs + buf * BK * BS_ST;
        #pragma unroll
        for (int s = 0; s < 4; s++) {
            int k0 = s * 8;
            unsigned af[4][4];
            #pragma unroll
            for (int mt = 0; mt < 4; mt++) {
                int r = wm * 64 + mt * 16 + g;
                af[mt][0] = __float_as_uint(Ab[r * AS_ST + k0 + tg]);
                af[mt][1] = __float_as_uint(Ab[(r + 8) * AS_ST + k0 + tg]);
                af[mt][2] = __float_as_uint(Ab[r * AS_ST + k0 + tg + 4]);
                af[mt][3] = __float_as_uint(Ab[(r + 8) * AS_ST + k0 + tg + 4]);
            }
            unsigned bf[4][2];
            #pragma unroll
            for (int nt = 0; nt < 4; nt++) {
                int n = wn * 32 + nt * 8 + g;
                bf[nt][0] = __float_as_uint(Bb[(k0 + tg) * BS_ST + n]);
                bf[nt][1] = __float_as_uint(Bb[(k0 + tg + 4) * BS_ST + n]);
            }
            #pragma unroll
            for (int mt = 0; mt < 4; mt++)
                #pragma unroll
                for (int nt = 0; nt < 4; nt++)
                    mma_tf32(acc[mt][nt], af[mt], bf[nt]);
        }
        __syncthreads();
    }

    #pragma unroll
    for (int mt = 0; mt < 4; mt++) {
        int m1 = row0 + wm * 64 + mt * 16 + g;
        int m2 = m1 + 8;
        #pragma unroll
        for (int nt = 0; nt < 4; nt++) {
            int n = col0 + wn * 32 + nt * 8 + 2 * tg;
            float2 bb = *reinterpret_cast<const float2*>(bias + n);
            float2 o1, o2;
            o1.x = acc[mt][nt][0] + bb.x;
            o1.y = acc[mt][nt][1] + bb.y;
            o2.x = acc[mt][nt][2] + bb.x;
            o2.y = acc[mt][nt][3] + bb.y;
            if (MODE == 2) {
                o1.x = roundtf(fmaxf(o1.x, 0.f)); o1.y = roundtf(fmaxf(o1.y, 0.f));
                o2.x = roundtf(fmaxf(o2.x, 0.f)); o2.y = roundtf(fmaxf(o2.y, 0.f));
                *reinterpret_cast<float2*>(C + (size_t)m1 * Ndim + n) = o1;
                *reinterpret_cast<float2*>(C + (size_t)m2 * Ndim + n) = o2;
            } else if (MODE == 3) {
                float2 r1 = *reinterpret_cast<const float2*>(res + (size_t)m1 * Ndim + n);
                float2 r2 = *reinterpret_cast<const float2*>(res + (size_t)m2 * Ndim + n);
                o1.x += r1.x; o1.y += r1.y;
                o2.x += r2.x; o2.y += r2.y;
                *reinterpret_cast<float2*>(C + (size_t)m1 * Ndim + n) = o1;
                *reinterpret_cast<float2*>(C + (size_t)m2 * Ndim + n) = o2;
            } else {
                // MODE 1 (QKV, Ndim=3072): which = 0:q 1:k 2:v(transposed)
                int which = n >> 10;
                int nn = n & 1023;
                int h_ = nn >> 6;
                int dd = nn & (HEAD_DIM - 1);
                int b1_ = m1 >> 11, s1_ = m1 & (SEQ - 1);
                int bh  = b1_ * N_HEADS + h_;
                if (which < 2) {
                    float* dstb = (which ? Ck : C)
                        + ((size_t)bh * SEQ + s1_) * HEAD_DIM + dd;
                    *reinterpret_cast<float2*>(dstb) = o1;
                    *reinterpret_cast<float2*>(dstb + 8 * HEAD_DIM) = o2;
                } else {
                    float* vb = Cv + ((size_t)bh * HEAD_DIM + dd) * SEQ + s1_;
                    vb[0]       = o1.x;
                    vb[SEQ]     = o1.y;
                    vb[8]       = o2.x;
                    vb[SEQ + 8] = o2.y;
                }
            }
        }
    }
}

// ---------------------------------------------------------------------------
// Flash attention, bf16 tensor cores (m16n8k16). 128 q-rows/block, 8 warps;
// each warp owns 16 full q-rows (warp-local softmax). P stays in registers
// (QK C-frag layout == PV A-frag layout). V consumed pre-transposed [d][s].
// All smem arrays are bf16x2 pairs with stride 36 (%32==4 -> bank 4g+tg).
// ---------------------------------------------------------------------------
#define QP 36
#define KP 36
#define VP 36
#define ATTN_SMEM ((128*QP + 64*KP + 64*VP) * 4)

__global__ __launch_bounds__(256) void attn_kernel(
    const float* __restrict__ Q, const float* __restrict__ K,
    const float* __restrict__ Vt, float* __restrict__ ctx)
{
    extern __shared__ unsigned smu[];
    unsigned* Qsp = smu;                 // [128][36]  (m x d-pairs)
    unsigned* Ksp = Qsp + 128 * QP;      // [64][36]   (kv x d-pairs)
    unsigned* Vsp = Ksp + 64 * KP;       // [64][36]   (d x kv-pairs)

    int bh   = blockIdx.y;
    int q0   = blockIdx.x * 128;
    int tid  = threadIdx.x;
    int lane = tid & 31;
    int warp = tid >> 5;
    int g    = lane >> 2;
    int tg   = lane & 3;
    int r0   = warp * 16 + g;

    const float* Qg  = Q  + ((size_t)bh * SEQ + q0) * HEAD_DIM;
    const float* Kg  = K  + (size_t)bh * SEQ * HEAD_DIM;
    const float* Vtg = Vt + (size_t)bh * HEAD_DIM * SEQ;   // [d][s]

    // stage Q (scaled by 1/8), packed bf16x2 along d
    #pragma unroll
    for (int p = 0; p < 8; p++) {
        int f = tid + p * 256, r = f >> 4, c = (f & 15) * 4;
        float4 v = *reinterpret_cast<const float4*>(Qg + (size_t)r * HEAD_DIM + c);
        Qsp[r * QP + (c >> 1)]     = packbf(v.x * 0.125f, v.y * 0.125f);
        Qsp[r * QP + (c >> 1) + 1] = packbf(v.z * 0.125f, v.w * 0.125f);
    }

    float m[2] = {-1e30f, -1e30f};
    float l[2] = {0.f, 0.f};
    float acc[8][4] = {};
    float s[8][4];

    for (int kt = 0; kt < SEQ; kt += 64) {
        __syncthreads();
        #pragma unroll
        for (int p = 0; p < 4; p++) {
            int f = tid + p * 256, r = f >> 4, c = (f & 15) * 4;
            float4 kv = *reinterpret_cast<const float4*>(Kg + (size_t)(kt + r) * HEAD_DIM + c);
            Ksp[r * KP + (c >> 1)]     = packbf(kv.x, kv.y);
            Ksp[r * KP + (c >> 1) + 1] = packbf(kv.z, kv.w);
            // Vt rows are d, columns are s
            float4 vv = *reinterpret_cast<const float4*>(Vtg + (size_t)r * SEQ + kt + c);
            Vsp[r * VP + (c >> 1)]     = packbf(vv.x, vv.y);
            Vsp[r * VP + (c >> 1) + 1] = packbf(vv.z, vv.w);
        }
        __syncthreads();

        // ---- S = Q K^T : 16 rows x 64 kv, 4 k16-steps x 8 n-tiles
        #pragma unroll
        for (int nt = 0; nt < 8; nt++)
            #pragma unroll
            for (int q_ = 0; q_ < 4; q_++) s[nt][q_] = 0.f;
        #pragma unroll
        for (int j = 0; j < 4; j++) {
            int p0 = j * 8;
            unsigned aq[4];
            aq[0] = Qsp[r0 * QP + p0 + tg];
            aq[1] = Qsp[(r0 + 8) * QP + p0 + tg];
            aq[2] = Qsp[r0 * QP + p0 + tg + 4];
            aq[3] = Qsp[(r0 + 8) * QP + p0 + tg + 4];
            #pragma unroll
            for (int nt = 0; nt < 8; nt++) {
                int n = nt * 8 + g;
                unsigned bk[2];
                bk[0] = Ksp[n * KP + p0 + tg];
                bk[1] = Ksp[n * KP + p0 + tg + 4];
                mma_bf16(s[nt], aq, bk);
            }
        }

        // ---- online softmax; exp values written back into s
        #pragma unroll
        for (int h2 = 0; h2 < 2; h2++) {
            float mx = -1e30f;
            #pragma unroll
            for (int nt = 0; nt < 8; nt++)
                mx = fmaxf(mx, fmaxf(s[nt][h2 * 2], s[nt][h2 * 2 + 1]));
            mx = fmaxf(mx, __shfl_xor_sync(0xffffffffu, mx, 1));
            mx = fmaxf(mx, __shfl_xor_sync(0xffffffffu, mx, 2));
            float mnew = fmaxf(m[h2], mx);
            float corr = __expf(m[h2] - mnew);
            m[h2] = mnew;
            float rs = 0.f;
            #pragma unroll
            for (int nt = 0; nt < 8; nt++) {
                float e0 = __expf(s[nt][h2 * 2]     - mnew);
                float e1 = __expf(s[nt][h2 * 2 + 1] - mnew);
                rs += e0 + e1;
                s[nt][h2 * 2]     = e0;
                s[nt][h2 * 2 + 1] = e1;
            }
            rs += __shfl_xor_sync(0xffffffffu, rs, 1);
            rs += __shfl_xor_sync(0xffffffffu, rs, 2);
            l[h2] = l[h2] * corr + rs;
            #pragma unroll
            for (int nt = 0; nt < 8; nt++) {
                acc[nt][h2 * 2]     *= corr;
                acc[nt][h2 * 2 + 1] *= corr;
            }
        }

        // ---- O += P V : P packed from registers (no smem)
        #pragma unroll
        for (int j = 0; j < 4; j++) {
            unsigned ap[4];
            ap[0] = packbf(s[2 * j][0],     s[2 * j][1]);
            ap[1] = packbf(s[2 * j][2],     s[2 * j][3]);
            ap[2] = packbf(s[2 * j + 1][0], s[2 * j + 1][1]);
            ap[3] = packbf(s[2 * j + 1][2], s[2 * j + 1][3]);
            int p0 = j * 8;
            #pragma unroll
            for (int nt = 0; nt < 8; nt++) {
                int n = nt * 8 + g;     // d column
                unsigned bv[2];
                bv[0] = Vsp[n * VP + p0 + tg];
                bv[1] = Vsp[n * VP + p0 + tg + 4];
                mma_bf16(acc[nt], ap, bv);
            }
        }
    }

    // write ctx[b, s, h*64+d] tf32-rounded (O-proj A input)
    int b_ = bh >> 4, h_ = bh & 15;
    #pragma unroll
    for (int h2 = 0; h2 < 2; h2++) {
        int row   = q0 + warp * 16 + h2 * 8 + g;
        float inv = 1.0f / l[h2];
        float* dst = ctx + ((size_t)(b_ * SEQ + row)) * D_MODEL + h_ * HEAD_DIM;
        #pragma unroll
        for (int nt = 0; nt < 8; nt++) {
            int cc = nt * 8 + 2 * tg;
            float2 o;
            o.x = roundtf(acc[nt][h2 * 2]     * inv);
            o.y = roundtf(acc[nt][h2 * 2 + 1] * inv);
            *reinterpret_cast<float2*>(dst + cc) = o;
        }
    }
}

// ---------------------------------------------------------------------------
// Launch
// ---------------------------------------------------------------------------
extern "C" void kernel_launch(void* const* d_in, const int* in_sizes, int n_in,
                              void* d_out, int out_size)
{
    const float* x   = (const float*)d_in[0];
    const float* wq  = (const float*)d_in[1];
    const float* bq  = (const float*)d_in[2];
    const float* wk  = (const float*)d_in[3];
    const float* bk  = (const float*)d_in[4];
    const float* wv  = (const float*)d_in[5];
    const float* bv  = (const float*)d_in[6];
    const float* wo  = (const float*)d_in[7];
    const float* bo  = (const float*)d_in[8];
    const float* w1  = (const float*)d_in[9];
    const float* b1  = (const float*)d_in[10];
    const float* w2  = (const float*)d_in[11];
    const float* b2  = (const float*)d_in[12];
    const float* g1  = (const float*)d_in[13];
    const float* be1 = (const float*)d_in[14];
    const float* g2  = (const float*)d_in[15];
    const float* be2 = (const float*)d_in[16];
    float* out = (float*)d_out;

    float *nx, *q, *k, *vt, *ctx, *x2, *nx2, *ffh;
    float *wqkv, *bqkv, *wor, *w1r, *w2r;
    cudaGetSymbolAddress((void**)&nx,   g_nx);
    cudaGetSymbolAddress((void**)&q,    g_q);
    cudaGetSymbolAddress((void**)&k,    g_k);
    cudaGetSymbolAddress((void**)&vt,   g_vt);
    cudaGetSymbolAddress((void**)&ctx,  g_ctx);
    cudaGetSymbolAddress((void**)&x2,   g_x2);
    cudaGetSymbolAddress((void**)&nx2,  g_nx2);
    cudaGetSymbolAddress((void**)&ffh,  g_ffh);
    cudaGetSymbolAddress((void**)&wqkv, g_wqkv);
    cudaGetSymbolAddress((void**)&bqkv, g_bqkv);
    cudaGetSymbolAddress((void**)&wor,  g_wor);
    cudaGetSymbolAddress((void**)&w1r,  g_w1r);
    cudaGetSymbolAddress((void**)&w2r,  g_w2r);

    cudaFuncSetAttribute(mmagemm_kernel<1>,
                         cudaFuncAttributeMaxDynamicSharedMemorySize, GEMM_SMEM);
    cudaFuncSetAttribute(mmagemm_kernel<2>,
                         cudaFuncAttributeMaxDynamicSharedMemorySize, GEMM_SMEM);
    cudaFuncSetAttribute(mmagemm_kernel<3>,
                         cudaFuncAttributeMaxDynamicSharedMemorySize, GEMM_SMEM);
    cudaFuncSetAttribute(attn_kernel,
                         cudaFuncAttributeMaxDynamicSharedMemorySize, ATTN_SMEM);

    // weight prep
    int nW  = D_MODEL * D_MODEL / 4;       // float4 count for 1024x1024
    int nDF = D_MODEL * D_FF / 4;
    wcat_kernel<<<nW / 256, 256>>>(wq, wqkv + 0);
    wcat_kernel<<<nW / 256, 256>>>(wk, wqkv + D_MODEL);
    wcat_kernel<<<nW / 256, 256>>>(wv, wqkv + 2 * D_MODEL);
    bcat_kernel<<<3, 256>>>(bq, bk, bv, bqkv);
    wround_kernel<<<(nW  + 255) / 256, 256>>>(wo, wor, nW);
    wround_kernel<<<(nDF + 255) / 256, 256>>>(w1, w1r, nDF);
    wround_kernel<<<(nDF + 255) / 256, 256>>>(w2, w2r, nDF);

    dim3 gQKV(3 * D_MODEL / BN, M_ROWS / BM);  // (24, 32)
    dim3 gD  (D_MODEL / BN,     M_ROWS / BM);  // (8, 32)
    dim3 gFF (D_FF / BN,        M_ROWS / BM);  // (32, 32)

    ln_kernel<<<M_ROWS, 256>>>(x, g1, be1, nx);
    mmagemm_kernel<1><<<gQKV, 256, GEMM_SMEM>>>(nx, wqkv, bqkv, nullptr,
                                                q, k, vt, 3 * D_MODEL, D_MODEL);
    attn_kernel<<<dim3(SEQ / 128, BATCH * N_HEADS), 256, ATTN_SMEM>>>(q, k, vt, ctx);
    mmagemm_kernel<3><<<gD, 256, GEMM_SMEM>>>(ctx, wor, bo, x,
                                              x2, nullptr, nullptr, D_MODEL, D_MODEL);
    ln_kernel<<<M_ROWS, 256>>>(x2, g2, be2, nx2);
    mmagemm_kernel<2><<<gFF, 256, GEMM_SMEM>>>(nx2, w1r, b1, nullptr,
                                               ffh, nullptr, nullptr, D_FF, D_MODEL);
    mmagemm_kernel<3><<<gD, 256, GEMM_SMEM>>>(ffh, w2r, b2, x2,
                                              out, nullptr, nullptr, D_MODEL, D_FF);
}

// round 13
// speedup vs baseline: 1.2243x; 1.0015x over previous
#include <cuda_runtime.h>
#include <math.h>

#define D_MODEL   1024
#define N_HEADS   16
#define HEAD_DIM  64
#define D_FF      4096
#define SEQ       2048
#define BATCH     2
#define M_ROWS    (BATCH * SEQ)   // 4096
#define EPS       1e-5f

// ---------------------------------------------------------------------------
// Scratch (device globals -- no allocations allowed)
// ---------------------------------------------------------------------------
__device__ float g_nx  [M_ROWS * D_MODEL];   // LN1 out (tf32-rounded)
__device__ float g_q   [M_ROWS * D_MODEL];   // [B,H,S,d]
__device__ float g_k   [M_ROWS * D_MODEL];   // [B,H,S,d]
__device__ float g_vt  [M_ROWS * D_MODEL];   // [B,H,d,S]  (transposed V)
__device__ float g_ctx [M_ROWS * D_MODEL];   // [B,S,D] (tf32-rounded)
__device__ float g_x2  [M_ROWS * D_MODEL];   // fp32 exact
__device__ float g_nx2 [M_ROWS * D_MODEL];   // tf32-rounded
__device__ float g_ffh [M_ROWS * D_FF];      // tf32-rounded

__device__ __forceinline__ unsigned f2tf32(float x) {
    unsigned y;
    asm("cvt.rna.tf32.f32 %0, %1;" : "=r"(y) : "f"(x));
    return y;
}
__device__ __forceinline__ float roundtf(float x) {
    return __uint_as_float(f2tf32(x));
}
// pack two f32 -> bf16x2 (lo in lower half, hi in upper half)
__device__ __forceinline__ unsigned packbf(float lo, float hi) {
    unsigned r;
    asm("cvt.rn.satfinite.bf16x2.f32 %0, %1, %2;" : "=r"(r) : "f"(hi), "f"(lo));
    return r;
}

__device__ __forceinline__ void mma_tf32(float* c, const unsigned* a, const unsigned* b) {
    asm volatile(
        "mma.sync.aligned.m16n8k8.row.col.f32.tf32.tf32.f32 "
        "{%0,%1,%2,%3}, {%4,%5,%6,%7}, {%8,%9}, {%0,%1,%2,%3};"
        : "+f"(c[0]), "+f"(c[1]), "+f"(c[2]), "+f"(c[3])
        : "r"(a[0]), "r"(a[1]), "r"(a[2]), "r"(a[3]),
          "r"(b[0]), "r"(b[1]));
}
__device__ __forceinline__ void mma_bf16(float* c, const unsigned* a, const unsigned* b) {
    asm volatile(
        "mma.sync.aligned.m16n8k16.row.col.f32.bf16.bf16.f32 "
        "{%0,%1,%2,%3}, {%4,%5,%6,%7}, {%8,%9}, {%0,%1,%2,%3};"
        : "+f"(c[0]), "+f"(c[1]), "+f"(c[2]), "+f"(c[3])
        : "r"(a[0]), "r"(a[1]), "r"(a[2]), "r"(a[3]),
          "r"(b[0]), "r"(b[1]));
}

#define CP_ASYNC16(dst, src) \
    asm volatile("cp.async.cg.shared.global [%0], [%1], 16;" :: "r"(dst), "l"(src))

// ---------------------------------------------------------------------------
// LayerNorm -> tf32-rounded output
// ---------------------------------------------------------------------------
__global__ __launch_bounds__(256) void ln_kernel(
    const float* __restrict__ x, const float* __restrict__ g,
    const float* __restrict__ b, float* __restrict__ out)
{
    int row = blockIdx.x;
    int t   = threadIdx.x;
    const float4* xr = reinterpret_cast<const float4*>(x + (size_t)row * D_MODEL);
    float4 v = xr[t];
    float s  = v.x + v.y + v.z + v.w;
    float ss = v.x * v.x + v.y * v.y + v.z * v.z + v.w * v.w;
    #pragma unroll
    for (int o = 16; o > 0; o >>= 1) {
        s  += __shfl_xor_sync(0xffffffffu, s,  o);
        ss += __shfl_xor_sync(0xffffffffu, ss, o);
    }
    __shared__ float shs[8], shss[8];
    int w = t >> 5;
    if ((t & 31) == 0) { shs[w] = s; shss[w] = ss; }
    __syncthreads();
    float tot = 0.f, tot2 = 0.f;
    #pragma unroll
    for (int i = 0; i < 8; i++) { tot += shs[i]; tot2 += shss[i]; }
    float mu  = tot * (1.0f / D_MODEL);
    float var = tot2 * (1.0f / D_MODEL) - mu * mu;
    float inv = rsqrtf(var + EPS);
    float4 gv = reinterpret_cast<const float4*>(g)[t];
    float4 bv = reinterpret_cast<const float4*>(b)[t];
    float4 o;
    o.x = roundtf((v.x - mu) * inv * gv.x + bv.x);
    o.y = roundtf((v.y - mu) * inv * gv.y + bv.y);
    o.z = roundtf((v.z - mu) * inv * gv.z + bv.z);
    o.w = roundtf((v.w - mu) * inv * gv.w + bv.w);
    reinterpret_cast<float4*>(out + (size_t)row * D_MODEL)[t] = o;
}

// ---------------------------------------------------------------------------
// TF32 GEMM: 128x128x32 tile, 8 warps, 3-stage cp.async pipeline with one
// barrier per k-iter. Weights read directly (cvt to tf32 at fragment load);
// A (activations) pre-rounded by producer epilogues.
// MODE 1: QKV (per-CTA weight/bias select; q/k head-scatter, v transposed);
// MODE 2: round(relu(acc+bias)); MODE 3: acc + bias + res (fp32 exact).
// ---------------------------------------------------------------------------
#define BM 128
#define BN 128
#define BK 32
#define AS_ST 36
#define BS_ST 136
#define STAGE_A (BM * AS_ST)
#define STAGE_B (BK * BS_ST)
#define GEMM_SMEM (3 * (STAGE_A + STAGE_B) * 4)

template<int MODE>
__global__ __launch_bounds__(256) void mmagemm_kernel(
    const float* __restrict__ A,
    const float* __restrict__ B0, const float* __restrict__ B1,
    const float* __restrict__ B2,
    const float* __restrict__ bias0, const float* __restrict__ bias1,
    const float* __restrict__ bias2,
    const float* __restrict__ res,
    float* __restrict__ C, float* __restrict__ Ck, float* __restrict__ Cv,
    int Ndim, int NdimB, int Kdim)
{
    extern __shared__ float smf[];
    float* As = smf;                    // [3][BM][AS_ST]
    float* Bs = smf + 3 * STAGE_A;      // [3][BK][BS_ST]

    int tid  = threadIdx.x;
    int lane = tid & 31;
    int warp = tid >> 5;
    int wm   = warp >> 2;
    int wn   = warp & 3;
    int g    = lane >> 2;
    int tg   = lane & 3;
    int row0 = blockIdx.y * BM;
    int col0 = blockIdx.x * BN;

    // per-CTA weight/bias select for fused QKV (128-col strip never straddles
    // a 1024 boundary)
    const float* Bp    = B0;
    const float* biasp = bias0;
    int colB = col0;
    if (MODE == 1) {
        int which = col0 >> 10;
        colB = col0 & 1023;
        Bp    = (which == 0) ? B0    : (which == 1) ? B1    : B2;
        biasp = (which == 0) ? bias0 : (which == 1) ? bias1 : bias2;
    }

    float acc[4][4][4] = {};

    auto issue_stage = [&](int kb, int slot) {
        float* Ab = As + slot * STAGE_A;
        float* Bb = Bs + slot * STAGE_B;
        #pragma unroll
        for (int p = 0; p < 4; p++) {
            int f = tid + p * 256, r = f >> 3, k4 = (f & 7) * 4;
            unsigned d = (unsigned)__cvta_generic_to_shared(Ab + r * AS_ST + k4);
            CP_ASYNC16(d, A + (size_t)(row0 + r) * Kdim + kb + k4);
        }
        #pragma unroll
        for (int p = 0; p < 4; p++) {
            int f = tid + p * 256, kk = f >> 5, n4 = (f & 31) * 4;
            unsigned d = (unsigned)__cvta_generic_to_shared(Bb + kk * BS_ST + n4);
            CP_ASYNC16(d, Bp + (size_t)(kb + kk) * NdimB + colB + n4);
        }
        asm volatile("cp.async.commit_group;");
    };

    int nk = Kdim / BK;
    issue_stage(0, 0);
    issue_stage(BK, 1);
    for (int t = 0; t < nk; t++) {
        if (t + 1 < nk) asm volatile("cp.async.wait_group 1;");
        else            asm volatile("cp.async.wait_group 0;");
        __syncthreads();
        if (t + 2 < nk) issue_stage((t + 2) * BK, (t + 2) % 3);

        int slot = t % 3;
        const float* Ab = As + slot * STAGE_A;
        const float* Bb = Bs + slot * STAGE_B;
        #pragma unroll
        for (int s = 0; s < 4; s++) {
            int k0 = s * 8;
            unsigned af[4][4];
            #pragma unroll
            for (int mt = 0; mt < 4; mt++) {
                int r = wm * 64 + mt * 16 + g;
                af[mt][0] = __float_as_uint(Ab[r * AS_ST + k0 + tg]);
                af[mt][1] = __float_as_uint(Ab[(r + 8) * AS_ST + k0 + tg]);
                af[mt][2] = __float_as_uint(Ab[r * AS_ST + k0 + tg + 4]);
                af[mt][3] = __float_as_uint(Ab[(r + 8) * AS_ST + k0 + tg + 4]);
            }
            unsigned bf[4][2];
            #pragma unroll
            for (int nt = 0; nt < 4; nt++) {
                int n = wn * 32 + nt * 8 + g;
                bf[nt][0] = f2tf32(Bb[(k0 + tg) * BS_ST + n]);
                bf[nt][1] = f2tf32(Bb[(k0 + tg + 4) * BS_ST + n]);
            }
            #pragma unroll
            for (int mt = 0; mt < 4; mt++)
                #pragma unroll
                for (int nt = 0; nt < 4; nt++)
                    mma_tf32(acc[mt][nt], af[mt], bf[nt]);
        }
    }

    #pragma unroll
    for (int mt = 0; mt < 4; mt++) {
        int m1 = row0 + wm * 64 + mt * 16 + g;
        int m2 = m1 + 8;
        #pragma unroll
        for (int nt = 0; nt < 4; nt++) {
            int n  = col0 + wn * 32 + nt * 8 + 2 * tg;
            int nl = (MODE == 1) ? (n & 1023) : n;
            float2 bb = *reinterpret_cast<const float2*>(biasp + nl);
            float2 o1, o2;
            o1.x = acc[mt][nt][0] + bb.x;
            o1.y = acc[mt][nt][1] + bb.y;
            o2.x = acc[mt][nt][2] + bb.x;
            o2.y = acc[mt][nt][3] + bb.y;
            if (MODE == 2) {
                o1.x = roundtf(fmaxf(o1.x, 0.f)); o1.y = roundtf(fmaxf(o1.y, 0.f));
                o2.x = roundtf(fmaxf(o2.x, 0.f)); o2.y = roundtf(fmaxf(o2.y, 0.f));
                *reinterpret_cast<float2*>(C + (size_t)m1 * Ndim + n) = o1;
                *reinterpret_cast<float2*>(C + (size_t)m2 * Ndim + n) = o2;
            } else if (MODE == 3) {
                float2 r1 = *reinterpret_cast<const float2*>(res + (size_t)m1 * Ndim + n);
                float2 r2 = *reinterpret_cast<const float2*>(res + (size_t)m2 * Ndim + n);
                o1.x += r1.x; o1.y += r1.y;
                o2.x += r2.x; o2.y += r2.y;
                *reinterpret_cast<float2*>(C + (size_t)m1 * Ndim + n) = o1;
                *reinterpret_cast<float2*>(C + (size_t)m2 * Ndim + n) = o2;
            } else {
                // MODE 1: which = 0:q 1:k 2:v(transposed)
                o1.x = roundtf(o1.x); o1.y = roundtf(o1.y);
                o2.x = roundtf(o2.x); o2.y = roundtf(o2.y);
                int which = n >> 10;
                int h_ = nl >> 6;
                int dd = nl & (HEAD_DIM - 1);
                int b1_ = m1 >> 11, s1_ = m1 & (SEQ - 1);
                int bh  = b1_ * N_HEADS + h_;
                if (which < 2) {
                    float* dstb = (which ? Ck : C)
                        + ((size_t)bh * SEQ + s1_) * HEAD_DIM + dd;
                    *reinterpret_cast<float2*>(dstb) = o1;
                    *reinterpret_cast<float2*>(dstb + 8 * HEAD_DIM) = o2;
                } else {
                    float* vb = Cv + ((size_t)bh * HEAD_DIM + dd) * SEQ + s1_;
                    vb[0]       = o1.x;
                    vb[SEQ]     = o1.y;
                    vb[8]       = o2.x;
                    vb[SEQ + 8] = o2.y;
                }
            }
        }
    }
}

// ---------------------------------------------------------------------------
// Flash attention, bf16 tensor cores (m16n8k16). 128 q-rows/block, 8 warps;
// each warp owns 16 full q-rows (warp-local softmax). P stays in registers
// (QK C-frag layout == PV A-frag layout). V consumed pre-transposed [d][s].
// ---------------------------------------------------------------------------
#define QP 36
#define KP 36
#define VP 36
#define ATTN_SMEM ((128*QP + 64*KP + 64*VP) * 4)

__global__ __launch_bounds__(256) void attn_kernel(
    const float* __restrict__ Q, const float* __restrict__ K,
    const float* __restrict__ Vt, float* __restrict__ ctx)
{
    extern __shared__ unsigned smu[];
    unsigned* Qsp = smu;                 // [128][36]  (m x d-pairs)
    unsigned* Ksp = Qsp + 128 * QP;      // [64][36]   (kv x d-pairs)
    unsigned* Vsp = Ksp + 64 * KP;       // [64][36]   (d x kv-pairs)

    int bh   = blockIdx.y;
    int q0   = blockIdx.x * 128;
    int tid  = threadIdx.x;
    int lane = tid & 31;
    int warp = tid >> 5;
    int g    = lane >> 2;
    int tg   = lane & 3;
    int r0   = warp * 16 + g;

    const float* Qg  = Q  + ((size_t)bh * SEQ + q0) * HEAD_DIM;
    const float* Kg  = K  + (size_t)bh * SEQ * HEAD_DIM;
    const float* Vtg = Vt + (size_t)bh * HEAD_DIM * SEQ;   // [d][s]

    #pragma unroll
    for (int p = 0; p < 8; p++) {
        int f = tid + p * 256, r = f >> 4, c = (f & 15) * 4;
        float4 v = *reinterpret_cast<const float4*>(Qg + (size_t)r * HEAD_DIM + c);
        Qsp[r * QP + (c >> 1)]     = packbf(v.x * 0.125f, v.y * 0.125f);
        Qsp[r * QP + (c >> 1) + 1] = packbf(v.z * 0.125f, v.w * 0.125f);
    }

    float m[2] = {-1e30f, -1e30f};
    float l[2] = {0.f, 0.f};
    float acc[8][4] = {};
    float s[8][4];

    for (int kt = 0; kt < SEQ; kt += 64) {
        __syncthreads();
        #pragma unroll
        for (int p = 0; p < 4; p++) {
            int f = tid + p * 256, r = f >> 4, c = (f & 15) * 4;
            float4 kv = *reinterpret_cast<const float4*>(Kg + (size_t)(kt + r) * HEAD_DIM + c);
            Ksp[r * KP + (c >> 1)]     = packbf(kv.x, kv.y);
            Ksp[r * KP + (c >> 1) + 1] = packbf(kv.z, kv.w);
            float4 vv = *reinterpret_cast<const float4*>(Vtg + (size_t)r * SEQ + kt + c);
            Vsp[r * VP + (c >> 1)]     = packbf(vv.x, vv.y);
            Vsp[r * VP + (c >> 1) + 1] = packbf(vv.z, vv.w);
        }
        __syncthreads();

        #pragma unroll
        for (int nt = 0; nt < 8; nt++)
            #pragma unroll
            for (int q_ = 0; q_ < 4; q_++) s[nt][q_] = 0.f;
        #pragma unroll
        for (int j = 0; j < 4; j++) {
            int p0 = j * 8;
            unsigned aq[4];
            aq[0] = Qsp[r0 * QP + p0 + tg];
            aq[1] = Qsp[(r0 + 8) * QP + p0 + tg];
            aq[2] = Qsp[r0 * QP + p0 + tg + 4];
            aq[3] = Qsp[(r0 + 8) * QP + p0 + tg + 4];
            #pragma unroll
            for (int nt = 0; nt < 8; nt++) {
                int n = nt * 8 + g;
                unsigned bk[2];
                bk[0] = Ksp[n * KP + p0 + tg];
                bk[1] = Ksp[n * KP + p0 + tg + 4];
                mma_bf16(s[nt], aq, bk);
            }
        }

        #pragma unroll
        for (int h2 = 0; h2 < 2; h2++) {
            float mx = -1e30f;
            #pragma unroll
            for (int nt = 0; nt < 8; nt++)
                mx = fmaxf(mx, fmaxf(s[nt][h2 * 2], s[nt][h2 * 2 + 1]));
            mx = fmaxf(mx, __shfl_xor_sync(0xffffffffu, mx, 1));
            mx = fmaxf(mx, __shfl_xor_sync(0xffffffffu, mx, 2));
            float mnew = fmaxf(m[h2], mx);
            float corr = __expf(m[h2] - mnew);
            m[h2] = mnew;
            float rs = 0.f;
            #pragma unroll
            for (int nt = 0; nt < 8; nt++) {
                float e0 = __expf(s[nt][h2 * 2]     - mnew);
                float e1 = __expf(s[nt][h2 * 2 + 1] - mnew);
                rs += e0 + e1;
                s[nt][h2 * 2]     = e0;
                s[nt][h2 * 2 + 1] = e1;
            }
            rs += __shfl_xor_sync(0xffffffffu, rs, 1);
            rs += __shfl_xor_sync(0xffffffffu, rs, 2);
            l[h2] = l[h2] * corr + rs;
            #pragma unroll
            for (int nt = 0; nt < 8; nt++) {
                acc[nt][h2 * 2]     *= corr;
                acc[nt][h2 * 2 + 1] *= corr;
            }
        }

        #pragma unroll
        for (int j = 0; j < 4; j++) {
            unsigned ap[4];
            ap[0] = packbf(s[2 * j][0],     s[2 * j][1]);
            ap[1] = packbf(s[2 * j][2],     s[2 * j][3]);
            ap[2] = packbf(s[2 * j + 1][0], s[2 * j + 1][1]);
            ap[3] = packbf(s[2 * j + 1][2], s[2 * j + 1][3]);
            int p0 = j * 8;
            #pragma unroll
            for (int nt = 0; nt < 8; nt++) {
                int n = nt * 8 + g;
                unsigned bv[2];
                bv[0] = Vsp[n * VP + p0 + tg];
                bv[1] = Vsp[n * VP + p0 + tg + 4];
                mma_bf16(acc[nt], ap, bv);
            }
        }
    }

    int b_ = bh >> 4, h_ = bh & 15;
    #pragma unroll
    for (int h2 = 0; h2 < 2; h2++) {
        int row   = q0 + warp * 16 + h2 * 8 + g;
        float inv = 1.0f / l[h2];
        float* dst = ctx + ((size_t)(b_ * SEQ + row)) * D_MODEL + h_ * HEAD_DIM;
        #pragma unroll
        for (int nt = 0; nt < 8; nt++) {
            int cc = nt * 8 + 2 * tg;
            float2 o;
            o.x = roundtf(acc[nt][h2 * 2]     * inv);
            o.y = roundtf(acc[nt][h2 * 2 + 1] * inv);
            *reinterpret_cast<float2*>(dst + cc) = o;
        }
    }
}

// ---------------------------------------------------------------------------
// Launch
// ---------------------------------------------------------------------------
extern "C" void kernel_launch(void* const* d_in, const int* in_sizes, int n_in,
                              void* d_out, int out_size)
{
    const float* x   = (const float*)d_in[0];
    const float* wq  = (const float*)d_in[1];
    const float* bq  = (const float*)d_in[2];
    const float* wk  = (const float*)d_in[3];
    const float* bk  = (const float*)d_in[4];
    const float* wv  = (const float*)d_in[5];
    const float* bv  = (const float*)d_in[6];
    const float* wo  = (const float*)d_in[7];
    const float* bo  = (const float*)d_in[8];
    const float* w1  = (const float*)d_in[9];
    const float* b1  = (const float*)d_in[10];
    const float* w2  = (const float*)d_in[11];
    const float* b2  = (const float*)d_in[12];
    const float* g1  = (const float*)d_in[13];
    const float* be1 = (const float*)d_in[14];
    const float* g2  = (const float*)d_in[15];
    const float* be2 = (const float*)d_in[16];
    float* out = (float*)d_out;

    float *nx, *q, *k, *vt, *ctx, *x2, *nx2, *ffh;
    cudaGetSymbolAddress((void**)&nx,   g_nx);
    cudaGetSymbolAddress((void**)&q,    g_q);
    cudaGetSymbolAddress((void**)&k,    g_k);
    cudaGetSymbolAddress((void**)&vt,   g_vt);
    cudaGetSymbolAddress((void**)&ctx,  g_ctx);
    cudaGetSymbolAddress((void**)&x2,   g_x2);
    cudaGetSymbolAddress((void**)&nx2,  g_nx2);
    cudaGetSymbolAddress((void**)&ffh,  g_ffh);

    cudaFuncSetAttribute(mmagemm_kernel<1>,
                         cudaFuncAttributeMaxDynamicSharedMemorySize, GEMM_SMEM);
    cudaFuncSetAttribute(mmagemm_kernel<2>,
                         cudaFuncAttributeMaxDynamicSharedMemorySize, GEMM_SMEM);
    cudaFuncSetAttribute(mmagemm_kernel<3>,
                         cudaFuncAttributeMaxDynamicSharedMemorySize, GEMM_SMEM);
    cudaFuncSetAttribute(attn_kernel,
                         cudaFuncAttributeMaxDynamicSharedMemorySize, ATTN_SMEM);

    dim3 gQKV(3 * D_MODEL / BN, M_ROWS / BM);  // (24, 32)
    dim3 gD  (D_MODEL / BN,     M_ROWS / BM);  // (8, 32)
    dim3 gFF (D_FF / BN,        M_ROWS / BM);  // (32, 32)

    ln_kernel<<<M_ROWS, 256>>>(x, g1, be1, nx);
    mmagemm_kernel<1><<<gQKV, 256, GEMM_SMEM>>>(
        nx, wq, wk, wv, bq, bk, bv, nullptr,
        q, k, vt, 3 * D_MODEL, D_MODEL, D_MODEL);
    attn_kernel<<<dim3(SEQ / 128, BATCH * N_HEADS), 256, ATTN_SMEM>>>(q, k, vt, ctx);
    mmagemm_kernel<3><<<gD, 256, GEMM_SMEM>>>(
        ctx, wo, nullptr, nullptr, bo, nullptr, nullptr, x,
        x2, nullptr, nullptr, D_MODEL, D_MODEL, D_MODEL);
    ln_kernel<<<M_ROWS, 256>>>(x2, g2, be2, nx2);
    mmagemm_kernel<2><<<gFF, 256, GEMM_SMEM>>>(
        nx2, w1, nullptr, nullptr, b1, nullptr, nullptr, nullptr,
        ffh, nullptr, nullptr, D_FF, D_FF, D_MODEL);
    mmagemm_kernel<3><<<gD, 256, GEMM_SMEM>>>(
        ffh, w2, nullptr, nullptr, b2, nullptr, nullptr, x2,
        out, nullptr, nullptr, D_MODEL, D_MODEL, D_FF);
}

// round 15
// speedup vs baseline: 1.3271x; 1.0840x over previous
#include <cuda_runtime.h>
#include <math.h>

#define D_MODEL   1024
#define N_HEADS   16
#define HEAD_DIM  64
#define D_FF      4096
#define SEQ       2048
#define BATCH     2
#define M_ROWS    (BATCH * SEQ)   // 4096
#define EPS       1e-5f

// ---------------------------------------------------------------------------
// Scratch (device globals -- no allocations allowed)
// ---------------------------------------------------------------------------
__device__ float g_nx  [M_ROWS * D_MODEL];   // LN1 out (tf32-rounded)
__device__ float g_q   [M_ROWS * D_MODEL];   // [B,H,S,d]
__device__ float g_k   [M_ROWS * D_MODEL];   // [B,H,S,d]
__device__ float g_vt  [M_ROWS * D_MODEL];   // [B,H,d,S]  (transposed V)
__device__ float g_ctx [M_ROWS * D_MODEL];   // [B,S,D] (tf32-rounded)
__device__ float g_x2  [M_ROWS * D_MODEL];   // fp32 exact
__device__ float g_nx2 [M_ROWS * D_MODEL];   // tf32-rounded
__device__ float g_ffh [M_ROWS * D_FF];      // tf32-rounded

__device__ __forceinline__ unsigned f2tf32(float x) {
    unsigned y;
    asm("cvt.rna.tf32.f32 %0, %1;" : "=r"(y) : "f"(x));
    return y;
}
__device__ __forceinline__ float roundtf(float x) {
    return __uint_as_float(f2tf32(x));
}
// pack two f32 -> bf16x2 (lo in lower half, hi in upper half)
__device__ __forceinline__ unsigned packbf(float lo, float hi) {
    unsigned r;
    asm("cvt.rn.satfinite.bf16x2.f32 %0, %1, %2;" : "=r"(r) : "f"(hi), "f"(lo));
    return r;
}

__device__ __forceinline__ void mma_tf32(float* c, const unsigned* a, const unsigned* b) {
    asm volatile(
        "mma.sync.aligned.m16n8k8.row.col.f32.tf32.tf32.f32 "
        "{%0,%1,%2,%3}, {%4,%5,%6,%7}, {%8,%9}, {%0,%1,%2,%3};"
        : "+f"(c[0]), "+f"(c[1]), "+f"(c[2]), "+f"(c[3])
        : "r"(a[0]), "r"(a[1]), "r"(a[2]), "r"(a[3]),
          "r"(b[0]), "r"(b[1]));
}
__device__ __forceinline__ void mma_bf16(float* c, const unsigned* a, const unsigned* b) {
    asm volatile(
        "mma.sync.aligned.m16n8k16.row.col.f32.bf16.bf16.f32 "
        "{%0,%1,%2,%3}, {%4,%5,%6,%7}, {%8,%9}, {%0,%1,%2,%3};"
        : "+f"(c[0]), "+f"(c[1]), "+f"(c[2]), "+f"(c[3])
        : "r"(a[0]), "r"(a[1]), "r"(a[2]), "r"(a[3]),
          "r"(b[0]), "r"(b[1]));
}

#define CP_ASYNC16(dst, src) \
    asm volatile("cp.async.cg.shared.global [%0], [%1], 16;" :: "r"(dst), "l"(src))

// ---------------------------------------------------------------------------
// LayerNorm -> tf32-rounded output
// ---------------------------------------------------------------------------
__global__ __launch_bounds__(256) void ln_kernel(
    const float* __restrict__ x, const float* __restrict__ g,
    const float* __restrict__ b, float* __restrict__ out)
{
    int row = blockIdx.x;
    int t   = threadIdx.x;
    const float4* xr = reinterpret_cast<const float4*>(x + (size_t)row * D_MODEL);
    float4 v = xr[t];
    float s  = v.x + v.y + v.z + v.w;
    float ss = v.x * v.x + v.y * v.y + v.z * v.z + v.w * v.w;
    #pragma unroll
    for (int o = 16; o > 0; o >>= 1) {
        s  += __shfl_xor_sync(0xffffffffu, s,  o);
        ss += __shfl_xor_sync(0xffffffffu, ss, o);
    }
    __shared__ float shs[8], shss[8];
    int w = t >> 5;
    if ((t & 31) == 0) { shs[w] = s; shss[w] = ss; }
    __syncthreads();
    float tot = 0.f, tot2 = 0.f;
    #pragma unroll
    for (int i = 0; i < 8; i++) { tot += shs[i]; tot2 += shss[i]; }
    float mu  = tot * (1.0f / D_MODEL);
    float var = tot2 * (1.0f / D_MODEL) - mu * mu;
    float inv = rsqrtf(var + EPS);
    float4 gv = reinterpret_cast<const float4*>(g)[t];
    float4 bv = reinterpret_cast<const float4*>(b)[t];
    float4 o;
    o.x = roundtf((v.x - mu) * inv * gv.x + bv.x);
    o.y = roundtf((v.y - mu) * inv * gv.y + bv.y);
    o.z = roundtf((v.z - mu) * inv * gv.z + bv.z);
    o.w = roundtf((v.w - mu) * inv * gv.w + bv.w);
    reinterpret_cast<float4*>(out + (size_t)row * D_MODEL)[t] = o;
}

// ---------------------------------------------------------------------------
// TF32 GEMM: 128x128x32 tile, 8 warps, 2-stage cp.async double buffer
// (128 regs -> 2 CTAs/SM, enforced via launch_bounds). Weights read
// directly (cvt at B-fragment load); A pre-rounded by producer epilogues.
// MODE 1: QKV (per-CTA weight/bias select; q/k head-scatter, v transposed);
// MODE 2: round(relu(acc+bias)); MODE 3: acc + bias + res (fp32 exact).
// ---------------------------------------------------------------------------
#define BM 128
#define BN 128
#define BK 32
#define AS_ST 36
#define BS_ST 136
#define STAGE_A (BM * AS_ST)
#define STAGE_B (BK * BS_ST)
#define GEMM_SMEM (2 * (STAGE_A + STAGE_B) * 4)

template<int MODE>
__global__ __launch_bounds__(256, 2) void mmagemm_kernel(
    const float* __restrict__ A,
    const float* __restrict__ B0, const float* __restrict__ B1,
    const float* __restrict__ B2,
    const float* __restrict__ bias0, const float* __restrict__ bias1,
    const float* __restrict__ bias2,
    const float* __restrict__ res,
    float* __restrict__ C, float* __restrict__ Ck, float* __restrict__ Cv,
    int Ndim, int NdimB, int Kdim)
{
    extern __shared__ float smf[];
    float* As = smf;                    // [2][BM][AS_ST]
    float* Bs = smf + 2 * STAGE_A;      // [2][BK][BS_ST]

    int tid  = threadIdx.x;
    int lane = tid & 31;
    int warp = tid >> 5;
    int wm   = warp >> 2;
    int wn   = warp & 3;
    int g    = lane >> 2;
    int tg   = lane & 3;
    int row0 = blockIdx.y * BM;
    int col0 = blockIdx.x * BN;

    // per-CTA weight/bias select for fused QKV (128-col strip never
    // straddles a 1024 boundary)
    const float* Bp    = B0;
    const float* biasp = bias0;
    int colB = col0;
    if (MODE == 1) {
        int which = col0 >> 10;
        colB = col0 & 1023;
        Bp    = (which == 0) ? B0    : (which == 1) ? B1    : B2;
        biasp = (which == 0) ? bias0 : (which == 1) ? bias1 : bias2;
    }

    float acc[4][4][4] = {};

    auto issue_stage = [&](int kb, int buf) {
        float* Ab = As + buf * STAGE_A;
        float* Bb = Bs + buf * STAGE_B;
        #pragma unroll
        for (int p = 0; p < 4; p++) {
            int f = tid + p * 256, r = f >> 3, k4 = (f & 7) * 4;
            unsigned d = (unsigned)__cvta_generic_to_shared(Ab + r * AS_ST + k4);
            CP_ASYNC16(d, A + (size_t)(row0 + r) * Kdim + kb + k4);
        }
        #pragma unroll
        for (int p = 0; p < 4; p++) {
            int f = tid + p * 256, kk = f >> 5, n4 = (f & 31) * 4;
            unsigned d = (unsigned)__cvta_generic_to_shared(Bb + kk * BS_ST + n4);
            CP_ASYNC16(d, Bp + (size_t)(kb + kk) * NdimB + colB + n4);
        }
        asm volatile("cp.async.commit_group;");
    };

    issue_stage(0, 0);
    int nk = Kdim / BK;
    for (int t = 0; t < nk; t++) {
        int buf = t & 1;
        if (t + 1 < nk) {
            issue_stage((t + 1) * BK, buf ^ 1);
            asm volatile("cp.async.wait_group 1;");
        } else {
            asm volatile("cp.async.wait_group 0;");
        }
        __syncthreads();
        const float* Ab = As + buf * STAGE_A;
        const float* Bb = Bs + buf * STAGE_B;
        #pragma unroll
        for (int s = 0; s < 4; s++) {
            int k0 = s * 8;
            unsigned af[4][4];
            #pragma unroll
            for (int mt = 0; mt < 4; mt++) {
                int r = wm * 64 + mt * 16 + g;
                af[mt][0] = __float_as_uint(Ab[r * AS_ST + k0 + tg]);
                af[mt][1] = __float_as_uint(Ab[(r + 8) * AS_ST + k0 + tg]);
                af[mt][2] = __float_as_uint(Ab[r * AS_ST + k0 + tg + 4]);
                af[mt][3] = __float_as_uint(Ab[(r + 8) * AS_ST + k0 + tg + 4]);
            }
            unsigned bf[4][2];
            #pragma unroll
            for (int nt = 0; nt < 4; nt++) {
                int n = wn * 32 + nt * 8 + g;
                bf[nt][0] = f2tf32(Bb[(k0 + tg) * BS_ST + n]);
                bf[nt][1] = f2tf32(Bb[(k0 + tg + 4) * BS_ST + n]);
            }
            #pragma unroll
            for (int mt = 0; mt < 4; mt++)
                #pragma unroll
                for (int nt = 0; nt < 4; nt++)
                    mma_tf32(acc[mt][nt], af[mt], bf[nt]);
        }
        __syncthreads();
    }

    #pragma unroll
    for (int mt = 0; mt < 4; mt++) {
        int m1 = row0 + wm * 64 + mt * 16 + g;
        int m2 = m1 + 8;
        #pragma unroll
        for (int nt = 0; nt < 4; nt++) {
            int n  = col0 + wn * 32 + nt * 8 + 2 * tg;
            int nl = (MODE == 1) ? (n & 1023) : n;
            float2 bb = *reinterpret_cast<const float2*>(biasp + nl);
            float2 o1, o2;
            o1.x = acc[mt][nt][0] + bb.x;
            o1.y = acc[mt][nt][1] + bb.y;
            o2.x = acc[mt][nt][2] + bb.x;
            o2.y = acc[mt][nt][3] + bb.y;
            if (MODE == 2) {
                o1.x = roundtf(fmaxf(o1.x, 0.f)); o1.y = roundtf(fmaxf(o1.y, 0.f));
                o2.x = roundtf(fmaxf(o2.x, 0.f)); o2.y = roundtf(fmaxf(o2.y, 0.f));
                *reinterpret_cast<float2*>(C + (size_t)m1 * Ndim + n) = o1;
                *reinterpret_cast<float2*>(C + (size_t)m2 * Ndim + n) = o2;
            } else if (MODE == 3) {
                float2 r1 = *reinterpret_cast<const float2*>(res + (size_t)m1 * Ndim + n);
                float2 r2 = *reinterpret_cast<const float2*>(res + (size_t)m2 * Ndim + n);
                o1.x += r1.x; o1.y += r1.y;
                o2.x += r2.x; o2.y += r2.y;
                *reinterpret_cast<float2*>(C + (size_t)m1 * Ndim + n) = o1;
                *reinterpret_cast<float2*>(C + (size_t)m2 * Ndim + n) = o2;
            } else {
                // MODE 1: which = 0:q 1:k 2:v(transposed)
                o1.x = roundtf(o1.x); o1.y = roundtf(o1.y);
                o2.x = roundtf(o2.x); o2.y = roundtf(o2.y);
                int which = n >> 10;
                int h_ = nl >> 6;
                int dd = nl & (HEAD_DIM - 1);
                int b1_ = m1 >> 11, s1_ = m1 & (SEQ - 1);
                int bh  = b1_ * N_HEADS + h_;
                if (which < 2) {
                    float* dstb = (which ? Ck : C)
                        + ((size_t)bh * SEQ + s1_) * HEAD_DIM + dd;
                    *reinterpret_cast<float2*>(dstb) = o1;
                    *reinterpret_cast<float2*>(dstb + 8 * HEAD_DIM) = o2;
                } else {
                    float* vb = Cv + ((size_t)bh * HEAD_DIM + dd) * SEQ + s1_;
                    vb[0]       = o1.x;
                    vb[SEQ]     = o1.y;
                    vb[8]       = o2.x;
                    vb[SEQ + 8] = o2.y;
                }
            }
        }
    }
}

// ---------------------------------------------------------------------------
// Flash attention, bf16 tensor cores (m16n8k16). 128 q-rows/block, 8 warps;
// each warp owns 16 full q-rows (warp-local softmax). P stays in registers
// (QK C-frag layout == PV A-frag layout). V consumed pre-transposed [d][s].
// ---------------------------------------------------------------------------
#define QP 36
#define KP 36
#define VP 36
#define ATTN_SMEM ((128*QP + 64*KP + 64*VP) * 4)

__global__ __launch_bounds__(256) void attn_kernel(
    const float* __restrict__ Q, const float* __restrict__ K,
    const float* __restrict__ Vt, float* __restrict__ ctx)
{
    extern __shared__ unsigned smu[];
    unsigned* Qsp = smu;                 // [128][36]  (m x d-pairs)
    unsigned* Ksp = Qsp + 128 * QP;      // [64][36]   (kv x d-pairs)
    unsigned* Vsp = Ksp + 64 * KP;       // [64][36]   (d x kv-pairs)

    int bh   = blockIdx.y;
    int q0   = blockIdx.x * 128;
    int tid  = threadIdx.x;
    int lane = tid & 31;
    int warp = tid >> 5;
    int g    = lane >> 2;
    int tg   = lane & 3;
    int r0   = warp * 16 + g;

    const float* Qg  = Q  + ((size_t)bh * SEQ + q0) * HEAD_DIM;
    const float* Kg  = K  + (size_t)bh * SEQ * HEAD_DIM;
    const float* Vtg = Vt + (size_t)bh * HEAD_DIM * SEQ;   // [d][s]

    #pragma unroll
    for (int p = 0; p < 8; p++) {
        int f = tid + p * 256, r = f >> 4, c = (f & 15) * 4;
        float4 v = *reinterpret_cast<const float4*>(Qg + (size_t)r * HEAD_DIM + c);
        Qsp[r * QP + (c >> 1)]     = packbf(v.x * 0.125f, v.y * 0.125f);
        Qsp[r * QP + (c >> 1) + 1] = packbf(v.z * 0.125f, v.w * 0.125f);
    }

    float m[2] = {-1e30f, -1e30f};
    float l[2] = {0.f, 0.f};
    float acc[8][4] = {};
    float s[8][4];

    for (int kt = 0; kt < SEQ; kt += 64) {
        __syncthreads();
        #pragma unroll
        for (int p = 0; p < 4; p++) {
            int f = tid + p * 256, r = f >> 4, c = (f & 15) * 4;
            float4 kv = *reinterpret_cast<const float4*>(Kg + (size_t)(kt + r) * HEAD_DIM + c);
            Ksp[r * KP + (c >> 1)]     = packbf(kv.x, kv.y);
            Ksp[r * KP + (c >> 1) + 1] = packbf(kv.z, kv.w);
            float4 vv = *reinterpret_cast<const float4*>(Vtg + (size_t)r * SEQ + kt + c);
            Vsp[r * VP + (c >> 1)]     = packbf(vv.x, vv.y);
            Vsp[r * VP + (c >> 1) + 1] = packbf(vv.z, vv.w);
        }
        __syncthreads();

        #pragma unroll
        for (int nt = 0; nt < 8; nt++)
            #pragma unroll
            for (int q_ = 0; q_ < 4; q_++) s[nt][q_] = 0.f;
        #pragma unroll
        for (int j = 0; j < 4; j++) {
            int p0 = j * 8;
            unsigned aq[4];
            aq[0] = Qsp[r0 * QP + p0 + tg];
            aq[1] = Qsp[(r0 + 8) * QP + p0 + tg];
            aq[2] = Qsp[r0 * QP + p0 + tg + 4];
            aq[3] = Qsp[(r0 + 8) * QP + p0 + tg + 4];
            #pragma unroll
            for (int nt = 0; nt < 8; nt++) {
                int n = nt * 8 + g;
                unsigned bk[2];
                bk[0] = Ksp[n * KP + p0 + tg];
                bk[1] = Ksp[n * KP + p0 + tg + 4];
                mma_bf16(s[nt], aq, bk);
            }
        }

        #pragma unroll
        for (int h2 = 0; h2 < 2; h2++) {
            float mx = -1e30f;
            #pragma unroll
            for (int nt = 0; nt < 8; nt++)
                mx = fmaxf(mx, fmaxf(s[nt][h2 * 2], s[nt][h2 * 2 + 1]));
            mx = fmaxf(mx, __shfl_xor_sync(0xffffffffu, mx, 1));
            mx = fmaxf(mx, __shfl_xor_sync(0xffffffffu, mx, 2));
            float mnew = fmaxf(m[h2], mx);
            float corr = __expf(m[h2] - mnew);
            m[h2] = mnew;
            float rs = 0.f;
            #pragma unroll
            for (int nt = 0; nt < 8; nt++) {
                float e0 = __expf(s[nt][h2 * 2]     - mnew);
                float e1 = __expf(s[nt][h2 * 2 + 1] - mnew);
                rs += e0 + e1;
                s[nt][h2 * 2]     = e0;
                s[nt][h2 * 2 + 1] = e1;
            }
            rs += __shfl_xor_sync(0xffffffffu, rs, 1);
            rs += __shfl_xor_sync(0xffffffffu, rs, 2);
            l[h2] = l[h2] * corr + rs;
            #pragma unroll
            for (int nt = 0; nt < 8; nt++) {
                acc[nt][h2 * 2]     *= corr;
                acc[nt][h2 * 2 + 1] *= corr;
            }
        }

        #pragma unroll
        for (int j = 0; j < 4; j++) {
            unsigned ap[4];
            ap[0] = packbf(s[2 * j][0],     s[2 * j][1]);
            ap[1] = packbf(s[2 * j][2],     s[2 * j][3]);
            ap[2] = packbf(s[2 * j + 1][0], s[2 * j + 1][1]);
            ap[3] = packbf(s[2 * j + 1][2], s[2 * j + 1][3]);
            int p0 = j * 8;
            #pragma unroll
            for (int nt = 0; nt < 8; nt++) {
                int n = nt * 8 + g;
                unsigned bv[2];
                bv[0] = Vsp[n * VP + p0 + tg];
                bv[1] = Vsp[n * VP + p0 + tg + 4];
                mma_bf16(acc[nt], ap, bv);
            }
        }
    }

    int b_ = bh >> 4, h_ = bh & 15;
    #pragma unroll
    for (int h2 = 0; h2 < 2; h2++) {
        int row   = q0 + warp * 16 + h2 * 8 + g;
        float inv = 1.0f / l[h2];
        float* dst = ctx + ((size_t)(b_ * SEQ + row)) * D_MODEL + h_ * HEAD_DIM;
        #pragma unroll
        for (int nt = 0; nt < 8; nt++) {
            int cc = nt * 8 + 2 * tg;
            float2 o;
            o.x = roundtf(acc[nt][h2 * 2]     * inv);
            o.y = roundtf(acc[nt][h2 * 2 + 1] * inv);
            *reinterpret_cast<float2*>(dst + cc) = o;
        }
    }
}

// ---------------------------------------------------------------------------
// Launch
// ---------------------------------------------------------------------------
extern "C" void kernel_launch(void* const* d_in, const int* in_sizes, int n_in,
                              void* d_out, int out_size)
{
    const float* x   = (const float*)d_in[0];
    const float* wq  = (const float*)d_in[1];
    const float* bq  = (const float*)d_in[2];
    const float* wk  = (const float*)d_in[3];
    const float* bk  = (const float*)d_in[4];
    const float* wv  = (const float*)d_in[5];
    const float* bv  = (const float*)d_in[6];
    const float* wo  = (const float*)d_in[7];
    const float* bo  = (const float*)d_in[8];
    const float* w1  = (const float*)d_in[9];
    const float* b1  = (const float*)d_in[10];
    const float* w2  = (const float*)d_in[11];
    const float* b2  = (const float*)d_in[12];
    const float* g1  = (const float*)d_in[13];
    const float* be1 = (const float*)d_in[14];
    const float* g2  = (const float*)d_in[15];
    const float* be2 = (const float*)d_in[16];
    float* out = (float*)d_out;

    float *nx, *q, *k, *vt, *ctx, *x2, *nx2, *ffh;
    cudaGetSymbolAddress((void**)&nx,   g_nx);
    cudaGetSymbolAddress((void**)&q,    g_q);
    cudaGetSymbolAddress((void**)&k,    g_k);
    cudaGetSymbolAddress((void**)&vt,   g_vt);
    cudaGetSymbolAddress((void**)&ctx,  g_ctx);
    cudaGetSymbolAddress((void**)&x2,   g_x2);
    cudaGetSymbolAddress((void**)&nx2,  g_nx2);
    cudaGetSymbolAddress((void**)&ffh,  g_ffh);

    cudaFuncSetAttribute(mmagemm_kernel<1>,
                         cudaFuncAttributeMaxDynamicSharedMemorySize, GEMM_SMEM);
    cudaFuncSetAttribute(mmagemm_kernel<2>,
                         cudaFuncAttributeMaxDynamicSharedMemorySize, GEMM_SMEM);
    cudaFuncSetAttribute(mmagemm_kernel<3>,
                         cudaFuncAttributeMaxDynamicSharedMemorySize, GEMM_SMEM);
    cudaFuncSetAttribute(attn_kernel,
                         cudaFuncAttributeMaxDynamicSharedMemorySize, ATTN_SMEM);

    dim3 gQKV(3 * D_MODEL / BN, M_ROWS / BM);  // (24, 32)
    dim3 gD  (D_MODEL / BN,     M_ROWS / BM);  // (8, 32)
    dim3 gFF (D_FF / BN,        M_ROWS / BM);  // (32, 32)

    ln_kernel<<<M_ROWS, 256>>>(x, g1, be1, nx);
    mmagemm_kernel<1><<<gQKV, 256, GEMM_SMEM>>>(
        nx, wq, wk, wv, bq, bk, bv, nullptr,
        q, k, vt, 3 * D_MODEL, D_MODEL, D_MODEL);
    attn_kernel<<<dim3(SEQ / 128, BATCH * N_HEADS), 256, ATTN_SMEM>>>(q, k, vt, ctx);
    mmagemm_kernel<3><<<gD, 256, GEMM_SMEM>>>(
        ctx, wo, nullptr, nullptr, bo, nullptr, nullptr, x,
        x2, nullptr, nullptr, D_MODEL, D_MODEL, D_MODEL);
    ln_kernel<<<M_ROWS, 256>>>(x2, g2, be2, nx2);
    mmagemm_kernel<2><<<gFF, 256, GEMM_SMEM>>>(
        nx2, w1, nullptr, nullptr, b1, nullptr, nullptr, nullptr,
        ffh, nullptr, nullptr, D_FF, D_FF, D_MODEL);
    mmagemm_kernel<3><<<gD, 256, GEMM_SMEM>>>(
        ffh, w2, nullptr, nullptr, b2, nullptr, nullptr, x2,
        out, nullptr, nullptr, D_MODEL, D_MODEL, D_FF);
}